// round 1
// baseline (speedup 1.0000x reference)
#include <cuda_runtime.h>
#include <cuda_bf16.h>
#include <math.h>

// Shapes (fixed by the problem)
#define NTOK 8192      // B*N = 4*2048
#define C    1024
#define E    6
#define L    100
#define R    16

// Scratch (device globals; no allocation allowed)
__device__ float g_tokens[E * L * C];   // [e,l,c]
__device__ float g_val[E * L * C];      // [e,l,d]
__device__ float g_u[NTOK * C];         // delta_f + x

// ---------------------------------------------------------------------------
// Kernel 1: tokens[e,l,c] = sum_r A[e,l,r] * B[e,r,c]
// grid = E*L blocks, 256 threads; each thread does 4 c's.
// ---------------------------------------------------------------------------
__global__ __launch_bounds__(256) void tokens_kernel(
    const float* __restrict__ A, const float* __restrict__ Bm)
{
    int el = blockIdx.x;          // e*L + l
    int e = el / L;
    __shared__ float sa[R];
    int tid = threadIdx.x;
    if (tid < R) sa[tid] = A[el * R + tid];
    __syncthreads();
    const float* Bp = Bm + (size_t)e * R * C;
    #pragma unroll
    for (int i = 0; i < 4; i++) {
        int c = tid + 256 * i;
        float acc = 0.f;
        #pragma unroll
        for (int r = 0; r < R; r++) acc += sa[r] * Bp[r * C + c];
        g_tokens[(size_t)el * C + c] = acc;
    }
}

// ---------------------------------------------------------------------------
// Kernel 2/4: generic tiled SGEMM: out = epilogue( Amat[M,K] @ W[N,K]^T )
// N = K = 1024 fixed. 128x128 tile, bK=16, 256 threads, 8x8 per thread.
// MODE 0: out[m,n] = acc + bias[n]                         (val = tokens@wt_w^T+wt_b)
// MODE 1: out[m,n] = feats[m,n] + (acc + bias[n]) * scale  (final)
// ---------------------------------------------------------------------------
template <int MODE>
__global__ __launch_bounds__(256) void gemm_bias_kernel(
    const float* __restrict__ Amat, const float* __restrict__ W,
    const float* __restrict__ bias, const float* __restrict__ feats,
    const float* __restrict__ scale_p, float* __restrict__ out, int M)
{
    __shared__ float As[16][132];
    __shared__ float Bs[16][132];

    int tid = threadIdx.x;
    int bm0 = blockIdx.y * 128;
    int bn0 = blockIdx.x * 128;
    int ty = tid >> 4;        // 0..15
    int tx = tid & 15;        // 0..15
    int lr = tid >> 2;        // 0..63 (load row)
    int lk = (tid & 3) << 2;  // 0,4,8,12 (load k offset)

    float acc[8][8];
    #pragma unroll
    for (int i = 0; i < 8; i++)
        #pragma unroll
        for (int j = 0; j < 8; j++) acc[i][j] = 0.f;

    for (int k0 = 0; k0 < C; k0 += 16) {
        #pragma unroll
        for (int h = 0; h < 2; h++) {
            int m = lr + 64 * h;
            int gm = bm0 + m;
            float4 va = make_float4(0.f, 0.f, 0.f, 0.f);
            if (gm < M)
                va = *(const float4*)(Amat + (size_t)gm * C + k0 + lk);
            As[lk + 0][m] = va.x; As[lk + 1][m] = va.y;
            As[lk + 2][m] = va.z; As[lk + 3][m] = va.w;

            int n = lr + 64 * h;
            float4 vb = *(const float4*)(W + (size_t)(bn0 + n) * C + k0 + lk);
            Bs[lk + 0][n] = vb.x; Bs[lk + 1][n] = vb.y;
            Bs[lk + 2][n] = vb.z; Bs[lk + 3][n] = vb.w;
        }
        __syncthreads();
        #pragma unroll
        for (int kk = 0; kk < 16; kk++) {
            float4 a0 = *(float4*)&As[kk][ty * 8];
            float4 a1 = *(float4*)&As[kk][ty * 8 + 4];
            float4 b0 = *(float4*)&Bs[kk][tx * 8];
            float4 b1 = *(float4*)&Bs[kk][tx * 8 + 4];
            float af[8] = {a0.x, a0.y, a0.z, a0.w, a1.x, a1.y, a1.z, a1.w};
            float bf[8] = {b0.x, b0.y, b0.z, b0.w, b1.x, b1.y, b1.z, b1.w};
            #pragma unroll
            for (int i = 0; i < 8; i++)
                #pragma unroll
                for (int j = 0; j < 8; j++)
                    acc[i][j] += af[i] * bf[j];
        }
        __syncthreads();
    }

    float sc = (MODE == 1) ? scale_p[0] : 0.f;
    #pragma unroll
    for (int i = 0; i < 8; i++) {
        int m = bm0 + ty * 8 + i;
        if (m >= M) continue;
        #pragma unroll
        for (int j = 0; j < 8; j++) {
            int n = bn0 + tx * 8 + j;
            size_t idx = (size_t)m * C + n;
            float v = acc[i][j] + bias[n];
            if (MODE == 0) {
                out[idx] = v;
            } else {
                out[idx] = feats[idx] + v * sc;
            }
        }
    }
}

// ---------------------------------------------------------------------------
// Kernel 3: per-token. logits -> argmax e*; attn over tokens[e*]; softmax;
// u = x + sum_{l>=1} attn[l]*val[e*,l,:]
// grid = NTOK blocks, 256 threads.
// ---------------------------------------------------------------------------
__global__ __launch_bounds__(256) void token_kernel(
    const float* __restrict__ x_all, const float* __restrict__ w_gate)
{
    int t = blockIdx.x;
    const float* x = x_all + (size_t)t * C;
    __shared__ float sx[C];
    __shared__ float s_attn[L + 4];
    __shared__ float s_log[8];
    __shared__ int s_e;

    int tid = threadIdx.x;
    int lane = tid & 31;
    int wid = tid >> 5;

    #pragma unroll
    for (int i = 0; i < 4; i++) sx[tid + 256 * i] = x[tid + 256 * i];
    __syncthreads();

    // logits: warp e computes x . w_gate[:, e]
    if (wid < E) {
        float acc = 0.f;
        for (int c = lane; c < C; c += 32) acc += sx[c] * w_gate[c * E + wid];
        #pragma unroll
        for (int o = 16; o; o >>= 1) acc += __shfl_xor_sync(0xffffffffu, acc, o);
        if (lane == 0) s_log[wid] = acc;
    }
    __syncthreads();
    if (tid == 0) {
        int best = 0; float bv = s_log[0];
        #pragma unroll
        for (int e = 1; e < E; e++)
            if (s_log[e] > bv) { bv = s_log[e]; best = e; }
        s_e = best;
    }
    __syncthreads();
    int e = s_e;

    // attn logits: x . tokens[e, l, :] * C^-0.5
    const float* tok = g_tokens + (size_t)e * L * C;
    for (int l = wid; l < L; l += 8) {
        const float* tr = tok + (size_t)l * C;
        float acc = 0.f;
        for (int c = lane; c < C; c += 32) acc += sx[c] * tr[c];
        #pragma unroll
        for (int o = 16; o; o >>= 1) acc += __shfl_xor_sync(0xffffffffu, acc, o);
        if (lane == 0) s_attn[l] = acc * 0.03125f;  // 1/sqrt(1024)
    }
    __syncthreads();

    // softmax over all L (warp 0)
    if (wid == 0) {
        float m = -INFINITY;
        for (int l = lane; l < L; l += 32) m = fmaxf(m, s_attn[l]);
        #pragma unroll
        for (int o = 16; o; o >>= 1) m = fmaxf(m, __shfl_xor_sync(0xffffffffu, m, o));
        float s = 0.f;
        for (int l = lane; l < L; l += 32) {
            float v = expf(s_attn[l] - m);
            s_attn[l] = v;
            s += v;
        }
        #pragma unroll
        for (int o = 16; o; o >>= 1) s += __shfl_xor_sync(0xffffffffu, s, o);
        float inv = 1.f / s;
        for (int l = lane; l < L; l += 32) s_attn[l] *= inv;
    }
    __syncthreads();

    // u[d] = x[d] + sum_{l=1..L-1} attn[l] * val[e,l,d]
    const float* val = g_val + (size_t)e * L * C;
    float acc[4];
    #pragma unroll
    for (int i = 0; i < 4; i++) acc[i] = sx[tid + 256 * i];
    for (int l = 1; l < L; l++) {
        float w = s_attn[l];
        const float* vr = val + (size_t)l * C;
        #pragma unroll
        for (int i = 0; i < 4; i++) acc[i] += w * vr[tid + 256 * i];
    }
    float* u = g_u + (size_t)t * C;
    #pragma unroll
    for (int i = 0; i < 4; i++) u[tid + 256 * i] = acc[i];
}

// ---------------------------------------------------------------------------
// Launch
// Inputs: 0 feats, 1 A, 2 B, 3 w_gate, 4 wt_w, 5 wt_b, 6 wd_w, 7 wd_b, 8 scale
// ---------------------------------------------------------------------------
extern "C" void kernel_launch(void* const* d_in, const int* in_sizes, int n_in,
                              void* d_out, int out_size)
{
    const float* feats  = (const float*)d_in[0];
    const float* A      = (const float*)d_in[1];
    const float* Bm     = (const float*)d_in[2];
    const float* w_gate = (const float*)d_in[3];
    const float* wt_w   = (const float*)d_in[4];
    const float* wt_b   = (const float*)d_in[5];
    const float* wd_w   = (const float*)d_in[6];
    const float* wd_b   = (const float*)d_in[7];
    const float* scale  = (const float*)d_in[8];
    float* out = (float*)d_out;

    float* tokens_p; cudaGetSymbolAddress((void**)&tokens_p, g_tokens);
    float* val_p;    cudaGetSymbolAddress((void**)&val_p, g_val);
    float* u_p;      cudaGetSymbolAddress((void**)&u_p, g_u);

    // 1) tokens = A @ B
    tokens_kernel<<<E * L, 256>>>(A, Bm);

    // 2) val = tokens @ wt_w^T + wt_b   (M = 600)
    {
        dim3 grid(C / 128, (E * L + 127) / 128);
        gemm_bias_kernel<0><<<grid, 256>>>(tokens_p, wt_w, wt_b,
                                           nullptr, nullptr, val_p, E * L);
    }

    // 3) per-token: gating + attn + delta_f accumulation -> u
    token_kernel<<<NTOK, 256>>>(feats, w_gate);

    // 4) out = feats + (u @ wd_w^T + wd_b) * scale
    {
        dim3 grid(C / 128, NTOK / 128);
        gemm_bias_kernel<1><<<grid, 256>>>(u_p, wd_w, wd_b,
                                           feats, scale, out, NTOK);
    }
}

// round 2
// speedup vs baseline: 2.0106x; 2.0106x over previous
#include <cuda_runtime.h>
#include <cuda_bf16.h>
#include <math.h>

// Shapes (fixed by the problem)
#define NTOK 8192      // B*N = 4*2048
#define C    1024
#define E    6
#define L    100
#define R    16

// Scratch (device globals; no allocation allowed)
__device__ float g_tokens[E * L * C];            // [e,l,c]
__device__ float g_val[E * L * C];               // [e,l,d]
__device__ float g_attn[NTOK * 128];             // softmaxed attn per token (l padded to 128, l=0 and l>=100 zeroed)
__device__ __nv_bfloat16 g_u[NTOK * C];          // u = x + delta_f, bf16
__device__ __nv_bfloat16 g_wd[C * C];            // wd_w in bf16
__device__ int g_idx[E * NTOK];                  // compacted token ids per expert
__device__ int g_cnt[E];                         // per-expert counts

// ---------------------------------------------------------------------------
// Kernel 1: tokens[e,l,c] = sum_r A[e,l,r] * B[e,r,c]
// ---------------------------------------------------------------------------
__global__ __launch_bounds__(256) void tokens_kernel(
    const float* __restrict__ A, const float* __restrict__ Bm)
{
    int el = blockIdx.x;          // e*L + l
    int e = el / L;
    __shared__ float sa[R];
    int tid = threadIdx.x;
    if (tid < R) sa[tid] = A[el * R + tid];
    __syncthreads();
    const float* Bp = Bm + (size_t)e * R * C;
    #pragma unroll
    for (int i = 0; i < 4; i++) {
        int c = tid + 256 * i;
        float acc = 0.f;
        #pragma unroll
        for (int r = 0; r < R; r++) acc += sa[r] * Bp[r * C + c];
        g_tokens[(size_t)el * C + c] = acc;
    }
}

// ---------------------------------------------------------------------------
// Kernel 2: val = tokens @ wt_w^T + wt_b. M=600, N=K=1024. 64x64 tiles.
// 256 threads, 4x4 outputs per thread.
// ---------------------------------------------------------------------------
__global__ __launch_bounds__(256) void val_gemm_kernel(
    const float* __restrict__ Amat, const float* __restrict__ W,
    const float* __restrict__ bias, float* __restrict__ out)
{
    __shared__ float As[16][68];
    __shared__ float Bs[16][68];
    const int M = E * L;  // 600
    int tid = threadIdx.x;
    int bm0 = blockIdx.y * 64;
    int bn0 = blockIdx.x * 64;
    int ty = tid >> 4;        // 0..15 -> m
    int tx = tid & 15;        // 0..15 -> n
    int lr = tid >> 2;        // 0..63
    int lk = (tid & 3) << 2;  // 0,4,8,12

    float acc[4][4];
    #pragma unroll
    for (int i = 0; i < 4; i++)
        #pragma unroll
        for (int j = 0; j < 4; j++) acc[i][j] = 0.f;

    for (int k0 = 0; k0 < C; k0 += 16) {
        int gm = bm0 + lr;
        float4 va = make_float4(0.f, 0.f, 0.f, 0.f);
        if (gm < M) va = *(const float4*)(Amat + (size_t)gm * C + k0 + lk);
        As[lk + 0][lr] = va.x; As[lk + 1][lr] = va.y;
        As[lk + 2][lr] = va.z; As[lk + 3][lr] = va.w;
        float4 vb = *(const float4*)(W + (size_t)(bn0 + lr) * C + k0 + lk);
        Bs[lk + 0][lr] = vb.x; Bs[lk + 1][lr] = vb.y;
        Bs[lk + 2][lr] = vb.z; Bs[lk + 3][lr] = vb.w;
        __syncthreads();
        #pragma unroll
        for (int kk = 0; kk < 16; kk++) {
            float4 a = *(float4*)&As[kk][ty * 4];
            float4 b = *(float4*)&Bs[kk][tx * 4];
            float af[4] = {a.x, a.y, a.z, a.w};
            float bf[4] = {b.x, b.y, b.z, b.w};
            #pragma unroll
            for (int i = 0; i < 4; i++)
                #pragma unroll
                for (int j = 0; j < 4; j++) acc[i][j] += af[i] * bf[j];
        }
        __syncthreads();
    }
    #pragma unroll
    for (int i = 0; i < 4; i++) {
        int m = bm0 + ty * 4 + i;
        if (m >= M) continue;
        #pragma unroll
        for (int j = 0; j < 4; j++) {
            int n = bn0 + tx * 4 + j;
            out[(size_t)m * C + n] = acc[i][j] + bias[n];
        }
    }
}

// ---------------------------------------------------------------------------
// Kernel 3: gating — per-token argmax expert, compact per-expert token lists.
// 8 tokens per block (one warp each). 1024 blocks.
// ---------------------------------------------------------------------------
__global__ __launch_bounds__(256) void gate_kernel(
    const float* __restrict__ x_all, const float* __restrict__ w_gate)
{
    __shared__ float sw[C * E];   // 24KB
    int tid = threadIdx.x;
    for (int i = tid; i < C * E; i += 256) sw[i] = w_gate[i];
    __syncthreads();
    int lane = tid & 31, wid = tid >> 5;
    int t = blockIdx.x * 8 + wid;
    const float* x = x_all + (size_t)t * C;
    float acc[E];
    #pragma unroll
    for (int e = 0; e < E; e++) acc[e] = 0.f;
    for (int c = lane; c < C; c += 32) {
        float xv = x[c];
        #pragma unroll
        for (int e = 0; e < E; e++) acc[e] += xv * sw[c * E + e];
    }
    #pragma unroll
    for (int e = 0; e < E; e++) {
        #pragma unroll
        for (int o = 16; o; o >>= 1) acc[e] += __shfl_xor_sync(0xffffffffu, acc[e], o);
    }
    if (lane == 0) {
        int best = 0; float bv = acc[0];
        #pragma unroll
        for (int e = 1; e < E; e++)
            if (acc[e] > bv) { bv = acc[e]; best = e; }
        int pos = atomicAdd(&g_cnt[best], 1);
        g_idx[best * NTOK + pos] = t;
    }
}

// ---------------------------------------------------------------------------
// Kernel 4: attn — per (expert, 32-token tile): S = Xg @ tokens_e^T * C^-0.5,
// row softmax over l=0..99, zero l=0 & l>=100, store by token id.
// grid = E*256, early exit past count. 256 threads, 4x4 per thread (32x128).
// ---------------------------------------------------------------------------
__global__ __launch_bounds__(256) void attn_kernel(const float* __restrict__ x_all)
{
    int e = blockIdx.x >> 8;
    int tile = blockIdx.x & 255;
    int cnt = g_cnt[e];
    if (tile * 32 >= cnt) return;

    __shared__ float As[16][36];
    __shared__ float Bs[16][132];
    __shared__ float S[32][132];
    __shared__ int sidx[32];

    int tid = threadIdx.x;
    if (tid < 32) {
        int slot = tile * 32 + tid;
        sidx[tid] = (slot < cnt) ? g_idx[e * NTOK + slot] : -1;
    }
    __syncthreads();

    int ty = tid >> 5;   // 0..7 -> 4 m rows
    int tx = tid & 31;   // 0..31 -> 4 n cols
    float acc[4][4];
    #pragma unroll
    for (int i = 0; i < 4; i++)
        #pragma unroll
        for (int j = 0; j < 4; j++) acc[i][j] = 0.f;

    const float* tok = g_tokens + (size_t)e * L * C;

    for (int k0 = 0; k0 < C; k0 += 16) {
        if (tid < 128) {
            int r = tid >> 2;            // 0..31 (token row)
            int lk = (tid & 3) << 2;
            int gi = sidx[r];
            float4 va = make_float4(0.f, 0.f, 0.f, 0.f);
            if (gi >= 0) va = *(const float4*)(x_all + (size_t)gi * C + k0 + lk);
            As[lk + 0][r] = va.x; As[lk + 1][r] = va.y;
            As[lk + 2][r] = va.z; As[lk + 3][r] = va.w;
        }
        #pragma unroll
        for (int it = 0; it < 2; it++) {
            int idx = tid + it * 256;    // 0..511
            int n = idx >> 2;            // 0..127 (l)
            int lk = (idx & 3) << 2;
            float4 vb = make_float4(0.f, 0.f, 0.f, 0.f);
            if (n < L) vb = *(const float4*)(tok + (size_t)n * C + k0 + lk);
            Bs[lk + 0][n] = vb.x; Bs[lk + 1][n] = vb.y;
            Bs[lk + 2][n] = vb.z; Bs[lk + 3][n] = vb.w;
        }
        __syncthreads();
        #pragma unroll
        for (int kk = 0; kk < 16; kk++) {
            float af[4];
            #pragma unroll
            for (int i = 0; i < 4; i++) af[i] = As[kk][ty * 4 + i];
            float4 b = *(float4*)&Bs[kk][tx * 4];
            float bf[4] = {b.x, b.y, b.z, b.w};
            #pragma unroll
            for (int i = 0; i < 4; i++)
                #pragma unroll
                for (int j = 0; j < 4; j++) acc[i][j] += af[i] * bf[j];
        }
        __syncthreads();
    }
    #pragma unroll
    for (int i = 0; i < 4; i++)
        #pragma unroll
        for (int j = 0; j < 4; j++)
            S[ty * 4 + i][tx * 4 + j] = acc[i][j] * 0.03125f;
    __syncthreads();

    // softmax per row (8 warps, 4 rows each)
    int lane = tid & 31, wid = tid >> 5;
    for (int r = wid; r < 32; r += 8) {
        int token = sidx[r];
        float* row = S[r];
        float mx = -INFINITY;
        for (int l = lane; l < L; l += 32) mx = fmaxf(mx, row[l]);
        #pragma unroll
        for (int o = 16; o; o >>= 1) mx = fmaxf(mx, __shfl_xor_sync(0xffffffffu, mx, o));
        float sum = 0.f;
        float v[4];
        #pragma unroll
        for (int q = 0; q < 4; q++) {
            int l = lane + q * 32;
            v[q] = (l < L) ? expf(row[l] - mx) : 0.f;
            sum += v[q];
        }
        #pragma unroll
        for (int o = 16; o; o >>= 1) sum += __shfl_xor_sync(0xffffffffu, sum, o);
        float inv = 1.f / sum;
        if (token >= 0) {
            #pragma unroll
            for (int q = 0; q < 4; q++) {
                int l = lane + q * 32;
                float w = (l >= 1 && l < L) ? v[q] * inv : 0.f;
                g_attn[(size_t)token * 128 + l] = w;
            }
        }
    }
}

// ---------------------------------------------------------------------------
// Kernel 5: combine — per (expert, 128-token tile, 128-col tile):
// u = x + attn @ val_e, store bf16 by token id.
// grid = E*64*8, early exit. 256 threads, 8x8 per thread. K=128 (padded).
// ---------------------------------------------------------------------------
__global__ __launch_bounds__(256) void combine_kernel(const float* __restrict__ x_all)
{
    int bx = blockIdx.x;
    int e = bx >> 9;             // /512
    int rem = bx & 511;
    int tile = rem >> 3;         // 0..63
    int n0 = (rem & 7) << 7;     // 0..896
    int cnt = g_cnt[e];
    if (tile * 128 >= cnt) return;

    __shared__ float As[16][132];   // attn [k][m]
    __shared__ float Bs[16][132];   // val  [k][n]
    __shared__ int sidx[128];

    int tid = threadIdx.x;
    if (tid < 128) {
        int slot = tile * 128 + tid;
        sidx[tid] = (slot < cnt) ? g_idx[e * NTOK + slot] : -1;
    }
    __syncthreads();

    int ty = tid >> 4;   // 0..15
    int tx = tid & 15;   // 0..15
    int lr = tid >> 2;   // 0..63
    int lk = (tid & 3) << 2;

    float acc[8][8];
    #pragma unroll
    for (int i = 0; i < 8; i++)
        #pragma unroll
        for (int j = 0; j < 8; j++) acc[i][j] = 0.f;

    const float* val = g_val + (size_t)e * L * C;

    for (int k0 = 0; k0 < 128; k0 += 16) {
        #pragma unroll
        for (int h = 0; h < 2; h++) {
            int m = lr + 64 * h;
            int gi = sidx[m];
            float4 va = make_float4(0.f, 0.f, 0.f, 0.f);
            if (gi >= 0) va = *(const float4*)(g_attn + (size_t)gi * 128 + k0 + lk);
            As[lk + 0][m] = va.x; As[lk + 1][m] = va.y;
            As[lk + 2][m] = va.z; As[lk + 3][m] = va.w;
        }
        #pragma unroll
        for (int it = 0; it < 2; it++) {
            int idx = tid + it * 256;     // 0..511
            int kk = idx >> 5;            // 0..15
            int c4 = (idx & 31) << 2;     // 0..124
            int k = k0 + kk;
            float4 vb = make_float4(0.f, 0.f, 0.f, 0.f);
            if (k < L) vb = *(const float4*)(val + (size_t)k * C + n0 + c4);
            Bs[kk][c4 + 0] = vb.x; Bs[kk][c4 + 1] = vb.y;
            Bs[kk][c4 + 2] = vb.z; Bs[kk][c4 + 3] = vb.w;
        }
        __syncthreads();
        #pragma unroll
        for (int kk = 0; kk < 16; kk++) {
            float af[8];
            #pragma unroll
            for (int i = 0; i < 8; i++) af[i] = As[kk][ty * 8 + i];
            float4 b0 = *(float4*)&Bs[kk][tx * 8];
            float4 b1 = *(float4*)&Bs[kk][tx * 8 + 4];
            float bf[8] = {b0.x, b0.y, b0.z, b0.w, b1.x, b1.y, b1.z, b1.w};
            #pragma unroll
            for (int i = 0; i < 8; i++)
                #pragma unroll
                for (int j = 0; j < 8; j++) acc[i][j] += af[i] * bf[j];
        }
        __syncthreads();
    }

    #pragma unroll
    for (int i = 0; i < 8; i++) {
        int m = ty * 8 + i;
        int gi = sidx[m];
        if (gi < 0) continue;
        #pragma unroll
        for (int j = 0; j < 8; j++) {
            int n = n0 + tx * 8 + j;
            float u = x_all[(size_t)gi * C + n] + acc[i][j];
            g_u[(size_t)gi * C + n] = __float2bfloat16(u);
        }
    }
}

// ---------------------------------------------------------------------------
// Kernel 6: convert wd_w (fp32 [n][k]) -> bf16
// ---------------------------------------------------------------------------
__global__ __launch_bounds__(256) void conv_wd_kernel(const float* __restrict__ W)
{
    int idx = blockIdx.x * 256 + threadIdx.x;   // 0..262143 float4s
    float4 v = *(const float4*)(W + (size_t)idx * 4);
    __nv_bfloat162 h0 = __float22bfloat162_rn(make_float2(v.x, v.y));
    __nv_bfloat162 h1 = __float22bfloat162_rn(make_float2(v.z, v.w));
    uint2 packed;
    packed.x = *(unsigned int*)&h0;
    packed.y = *(unsigned int*)&h1;
    *(uint2*)(g_wd + (size_t)idx * 4) = packed;
}

// ---------------------------------------------------------------------------
// Kernel 7: final bf16 HMMA GEMM:
// out[m,n] = feats[m,n] + (sum_k u[m,k]*wd[n,k] + bias[n]) * scale
// M=8192, N=1024, K=1024. 128x128x32 tiles, 8 warps (4m x 2n), warp 32x64,
// mma m16n8k16. grid = (8, 64).
// ---------------------------------------------------------------------------
__global__ __launch_bounds__(256) void final_mma_kernel(
    const float* __restrict__ bias, const float* __restrict__ feats,
    const float* __restrict__ scale_p, float* __restrict__ out)
{
    __shared__ __nv_bfloat16 As[128][40];
    __shared__ __nv_bfloat16 Bs[128][40];

    int tid = threadIdx.x;
    int wid = tid >> 5, lane = tid & 31;
    int wm = (wid & 3) * 32;
    int wn = (wid >> 2) * 64;
    int bm0 = blockIdx.y * 128;
    int bn0 = blockIdx.x * 128;

    float acc[2][8][4];
    #pragma unroll
    for (int mi = 0; mi < 2; mi++)
        #pragma unroll
        for (int ni = 0; ni < 8; ni++)
            #pragma unroll
            for (int q = 0; q < 4; q++) acc[mi][ni][q] = 0.f;

    for (int k0 = 0; k0 < 1024; k0 += 32) {
        #pragma unroll
        for (int it = 0; it < 2; it++) {
            int idx = tid + it * 256;     // 0..511
            int r = idx >> 2;             // 0..127
            int c = (idx & 3) << 3;       // 0,8,16,24
            *(int4*)&As[r][c] = *(const int4*)(g_u + (size_t)(bm0 + r) * 1024 + k0 + c);
            *(int4*)&Bs[r][c] = *(const int4*)(g_wd + (size_t)(bn0 + r) * 1024 + k0 + c);
        }
        __syncthreads();
        #pragma unroll
        for (int ks = 0; ks < 32; ks += 16) {
            unsigned a[2][4], b[8][2];
            #pragma unroll
            for (int mi = 0; mi < 2; mi++) {
                unsigned addr = (unsigned)__cvta_generic_to_shared(
                    &As[wm + mi * 16 + (lane & 15)][ks + ((lane >> 4) << 3)]);
                asm volatile("ldmatrix.sync.aligned.m8n8.x4.shared.b16 {%0,%1,%2,%3}, [%4];"
                    : "=r"(a[mi][0]), "=r"(a[mi][1]), "=r"(a[mi][2]), "=r"(a[mi][3])
                    : "r"(addr));
            }
            #pragma unroll
            for (int nj = 0; nj < 4; nj++) {
                unsigned addr = (unsigned)__cvta_generic_to_shared(
                    &Bs[wn + nj * 16 + ((lane >> 4) << 3) + (lane & 7)]
                       [ks + (((lane >> 3) & 1) << 3)]);
                asm volatile("ldmatrix.sync.aligned.m8n8.x4.shared.b16 {%0,%1,%2,%3}, [%4];"
                    : "=r"(b[nj * 2][0]), "=r"(b[nj * 2][1]),
                      "=r"(b[nj * 2 + 1][0]), "=r"(b[nj * 2 + 1][1])
                    : "r"(addr));
            }
            #pragma unroll
            for (int mi = 0; mi < 2; mi++)
                #pragma unroll
                for (int ni = 0; ni < 8; ni++)
                    asm volatile(
                        "mma.sync.aligned.m16n8k16.row.col.f32.bf16.bf16.f32 "
                        "{%0,%1,%2,%3}, {%4,%5,%6,%7}, {%8,%9}, {%0,%1,%2,%3};"
                        : "+f"(acc[mi][ni][0]), "+f"(acc[mi][ni][1]),
                          "+f"(acc[mi][ni][2]), "+f"(acc[mi][ni][3])
                        : "r"(a[mi][0]), "r"(a[mi][1]), "r"(a[mi][2]), "r"(a[mi][3]),
                          "r"(b[ni][0]), "r"(b[ni][1]));
        }
        __syncthreads();
    }

    float sc = scale_p[0];
    int grp = lane >> 2, qid = lane & 3;
    #pragma unroll
    for (int mi = 0; mi < 2; mi++) {
        #pragma unroll
        for (int ni = 0; ni < 8; ni++) {
            int m = bm0 + wm + mi * 16 + grp;
            int n = bn0 + wn + ni * 8 + qid * 2;
            size_t i0 = (size_t)m * 1024 + n;
            size_t i1 = (size_t)(m + 8) * 1024 + n;
            float b0 = bias[n], b1 = bias[n + 1];
            out[i0]     = feats[i0]     + (acc[mi][ni][0] + b0) * sc;
            out[i0 + 1] = feats[i0 + 1] + (acc[mi][ni][1] + b1) * sc;
            out[i1]     = feats[i1]     + (acc[mi][ni][2] + b0) * sc;
            out[i1 + 1] = feats[i1 + 1] + (acc[mi][ni][3] + b1) * sc;
        }
    }
}

// ---------------------------------------------------------------------------
// Launch
// Inputs: 0 feats, 1 A, 2 B, 3 w_gate, 4 wt_w, 5 wt_b, 6 wd_w, 7 wd_b, 8 scale
// ---------------------------------------------------------------------------
extern "C" void kernel_launch(void* const* d_in, const int* in_sizes, int n_in,
                              void* d_out, int out_size)
{
    const float* feats  = (const float*)d_in[0];
    const float* A      = (const float*)d_in[1];
    const float* Bm     = (const float*)d_in[2];
    const float* w_gate = (const float*)d_in[3];
    const float* wt_w   = (const float*)d_in[4];
    const float* wt_b   = (const float*)d_in[5];
    const float* wd_w   = (const float*)d_in[6];
    const float* wd_b   = (const float*)d_in[7];
    const float* scale  = (const float*)d_in[8];
    float* out = (float*)d_out;

    float* tokens_p; cudaGetSymbolAddress((void**)&tokens_p, g_tokens);
    float* val_p;    cudaGetSymbolAddress((void**)&val_p, g_val);
    int* cnt_p;      cudaGetSymbolAddress((void**)&cnt_p, g_cnt);

    cudaMemsetAsync(cnt_p, 0, E * sizeof(int));

    // 1) tokens = A @ B
    tokens_kernel<<<E * L, 256>>>(A, Bm);

    // 2) val = tokens @ wt_w^T + wt_b
    val_gemm_kernel<<<dim3(C / 64, (E * L + 63) / 64), 256>>>(tokens_p, wt_w, wt_b, val_p);

    // 3) gating + per-expert compaction
    gate_kernel<<<NTOK / 8, 256>>>(feats, w_gate);

    // 4) attn = softmax(Xg @ tokens_e^T / sqrt(C))
    attn_kernel<<<E * 256, 256>>>(feats);

    // 5) u = x + attn @ val_e  (bf16)
    combine_kernel<<<E * 64 * 8, 256>>>(feats);

    // 6) wd_w -> bf16
    conv_wd_kernel<<<1024, 256>>>(wd_w);

    // 7) out = feats + (u @ wd^T + wd_b) * scale   (HMMA)
    final_mma_kernel<<<dim3(8, 64), 256>>>(wd_b, feats, scale, out);
}

// round 3
// speedup vs baseline: 3.5907x; 1.7859x over previous
#include <cuda_runtime.h>
#include <cuda_bf16.h>
#include <math.h>

#define NTOK 8192
#define C    1024
#define E    6
#define L    100
#define LP   128      // L padded

// Scratch
__device__ float g_tokens[E * L * C];                 // fp32 tokens [e][l][c]
__device__ __nv_bfloat16 g_tokb[E * LP * C];          // bf16 tokens, L-padded
__device__ __nv_bfloat16 g_valb[E * C * LP];          // bf16 val, TRANSPOSED [e][c][l]
__device__ __nv_bfloat16 g_xb[NTOK * C];              // bf16 feats
__device__ __nv_bfloat16 g_attnb[NTOK * LP];          // bf16 softmaxed attn
__device__ __nv_bfloat16 g_u[NTOK * C];               // bf16 u = x + delta_f
__device__ __nv_bfloat16 g_wd[C * C];                 // bf16 wd_w
__device__ int g_idx[E * NTOK];
__device__ int g_cnt[E];

// ---------------------------------------------------------------------------
// cp.async helpers
// ---------------------------------------------------------------------------
__device__ __forceinline__ void cp16(void* smem, const void* gmem) {
    unsigned s = (unsigned)__cvta_generic_to_shared(smem);
    asm volatile("cp.async.cg.shared.global [%0], [%1], 16;\n" :: "r"(s), "l"(gmem));
}
__device__ __forceinline__ void cp16z(void* smem, const void* gmem, bool valid) {
    unsigned s = (unsigned)__cvta_generic_to_shared(smem);
    int sz = valid ? 16 : 0;
    asm volatile("cp.async.cg.shared.global [%0], [%1], 16, %2;\n" :: "r"(s), "l"(gmem), "r"(sz));
}
#define CP_COMMIT() asm volatile("cp.async.commit_group;\n")
#define CP_WAIT1()  asm volatile("cp.async.wait_group 1;\n")
#define CP_WAIT0()  asm volatile("cp.async.wait_group 0;\n")

// ---------------------------------------------------------------------------
// Kernel 1: fused feats->bf16 conversion + gating (fp32 logits, exact argmax)
// 8 tokens/block (one warp each), 1024 blocks.
// ---------------------------------------------------------------------------
__global__ __launch_bounds__(256) void conv_gate_kernel(
    const float* __restrict__ feats, const float* __restrict__ w_gate)
{
    __shared__ float sw[E * C];   // transposed: sw[e*1024 + c]
    int tid = threadIdx.x;
    for (int i = tid; i < E * C; i += 256) {
        int e = i >> 10, c = i & 1023;
        sw[i] = w_gate[c * E + e];
    }
    __syncthreads();
    int lane = tid & 31, wid = tid >> 5;
    int t = blockIdx.x * 8 + wid;
    const float* x = feats + (size_t)t * C;
    __nv_bfloat16* xb = g_xb + (size_t)t * C;

    float acc[E];
    #pragma unroll
    for (int e = 0; e < E; e++) acc[e] = 0.f;

    #pragma unroll
    for (int i = 0; i < 8; i++) {
        int c0 = 4 * (lane + 32 * i);
        float4 v = *(const float4*)(x + c0);
        __nv_bfloat162 h0 = __float22bfloat162_rn(make_float2(v.x, v.y));
        __nv_bfloat162 h1 = __float22bfloat162_rn(make_float2(v.z, v.w));
        uint2 p; p.x = *(unsigned*)&h0; p.y = *(unsigned*)&h1;
        *(uint2*)(xb + c0) = p;
        #pragma unroll
        for (int e = 0; e < E; e++) {
            float4 w = *(const float4*)&sw[e * C + c0];
            acc[e] += v.x * w.x + v.y * w.y + v.z * w.z + v.w * w.w;
        }
    }
    #pragma unroll
    for (int e = 0; e < E; e++)
        #pragma unroll
        for (int o = 16; o; o >>= 1) acc[e] += __shfl_xor_sync(0xffffffffu, acc[e], o);
    if (lane == 0) {
        int best = 0; float bv = acc[0];
        #pragma unroll
        for (int e = 1; e < E; e++)
            if (acc[e] > bv) { bv = acc[e]; best = e; }
        int pos = atomicAdd(&g_cnt[best], 1);
        g_idx[best * NTOK + pos] = t;
    }
}

// ---------------------------------------------------------------------------
// Kernel 2: tokens[e,l,c] = sum_r A[e,l,r]*B[e,r,c]; fp32 + bf16(padded) out.
// grid = E*128.
// ---------------------------------------------------------------------------
__global__ __launch_bounds__(256) void tokens_kernel(
    const float* __restrict__ A, const float* __restrict__ Bm)
{
    int b = blockIdx.x;
    int e = b >> 7, l = b & 127;
    int tid = threadIdx.x;
    if (l >= L) {
        __nv_bfloat16 z = __float2bfloat16(0.f);
        #pragma unroll
        for (int i = 0; i < 4; i++)
            g_tokb[((size_t)(e * LP + l)) * C + tid + 256 * i] = z;
        return;
    }
    __shared__ float sa[16];
    if (tid < 16) sa[tid] = A[(e * L + l) * 16 + tid];
    __syncthreads();
    const float* Bp = Bm + (size_t)e * 16 * C;
    #pragma unroll
    for (int i = 0; i < 4; i++) {
        int c = tid + 256 * i;
        float acc = 0.f;
        #pragma unroll
        for (int r = 0; r < 16; r++) acc += sa[r] * Bp[r * C + c];
        g_tokens[((size_t)(e * L + l)) * C + c] = acc;
        g_tokb[((size_t)(e * LP + l)) * C + c] = __float2bfloat16(acc);
    }
}

// ---------------------------------------------------------------------------
// Kernel 3: val = tokens @ wt_w^T + wt_b, fp32 compute, output bf16
// TRANSPOSED+padded: g_valb[e][n][l], zeros for l>=100.
// grid (16, 2, E), 64x64 tiles.
// ---------------------------------------------------------------------------
__global__ __launch_bounds__(256) void val_gemm_kernel(
    const float* __restrict__ W, const float* __restrict__ bias)
{
    __shared__ float As[16][68];
    __shared__ float Bs[16][68];
    int e = blockIdx.z;
    const float* Amat = g_tokens + (size_t)e * L * C;
    int tid = threadIdx.x;
    int bm0 = blockIdx.y * 64;
    int bn0 = blockIdx.x * 64;
    int ty = tid >> 4, tx = tid & 15;
    int lr = tid >> 2, lk = (tid & 3) << 2;

    float acc[4][4];
    #pragma unroll
    for (int i = 0; i < 4; i++)
        #pragma unroll
        for (int j = 0; j < 4; j++) acc[i][j] = 0.f;

    for (int k0 = 0; k0 < C; k0 += 16) {
        int gm = bm0 + lr;
        float4 va = make_float4(0.f, 0.f, 0.f, 0.f);
        if (gm < L) va = *(const float4*)(Amat + (size_t)gm * C + k0 + lk);
        As[lk + 0][lr] = va.x; As[lk + 1][lr] = va.y;
        As[lk + 2][lr] = va.z; As[lk + 3][lr] = va.w;
        float4 vb = *(const float4*)(W + (size_t)(bn0 + lr) * C + k0 + lk);
        Bs[lk + 0][lr] = vb.x; Bs[lk + 1][lr] = vb.y;
        Bs[lk + 2][lr] = vb.z; Bs[lk + 3][lr] = vb.w;
        __syncthreads();
        #pragma unroll
        for (int kk = 0; kk < 16; kk++) {
            float4 a = *(float4*)&As[kk][ty * 4];
            float4 b = *(float4*)&Bs[kk][tx * 4];
            float af[4] = {a.x, a.y, a.z, a.w};
            float bf[4] = {b.x, b.y, b.z, b.w};
            #pragma unroll
            for (int i = 0; i < 4; i++)
                #pragma unroll
                for (int j = 0; j < 4; j++) acc[i][j] += af[i] * bf[j];
        }
        __syncthreads();
    }
    #pragma unroll
    for (int i = 0; i < 4; i++) {
        int l = bm0 + ty * 4 + i;
        #pragma unroll
        for (int j = 0; j < 4; j++) {
            int n = bn0 + tx * 4 + j;
            float v = (l < L) ? acc[i][j] + bias[n] : 0.f;
            g_valb[((size_t)e * C + n) * LP + l] = __float2bfloat16(v);
        }
    }
}

// ---------------------------------------------------------------------------
// Kernel 4: wd_w -> bf16
// ---------------------------------------------------------------------------
__global__ __launch_bounds__(256) void conv_wd_kernel(const float* __restrict__ W)
{
    int idx = blockIdx.x * 256 + threadIdx.x;
    float4 v = *(const float4*)(W + (size_t)idx * 4);
    __nv_bfloat162 h0 = __float22bfloat162_rn(make_float2(v.x, v.y));
    __nv_bfloat162 h1 = __float22bfloat162_rn(make_float2(v.z, v.w));
    uint2 p; p.x = *(unsigned*)&h0; p.y = *(unsigned*)&h1;
    *(uint2*)(g_wd + (size_t)idx * 4) = p;
}

// ---------------------------------------------------------------------------
// Kernel 5: attn (bf16 HMMA). Per (expert, 32-token tile):
// S = Xg @ tok_e^T / 32, softmax, store bf16 (l=0 and l>=100 zeroed).
// 8 warps: wm=(wid&1)*16, wn=(wid>>1)*32. cp.async double-buffered.
// ---------------------------------------------------------------------------
__global__ __launch_bounds__(256) void attn_kernel()
{
    int e = blockIdx.x >> 8;
    int tile = blockIdx.x & 255;
    int cnt = g_cnt[e];
    if (tile * 32 >= cnt) return;

    __shared__ __nv_bfloat16 As[2][32][40];
    __shared__ __nv_bfloat16 Bs[2][128][40];
    __shared__ float S[32][132];
    __shared__ int sidx[32];

    int tid = threadIdx.x;
    if (tid < 32) {
        int slot = tile * 32 + tid;
        sidx[tid] = (slot < cnt) ? g_idx[e * NTOK + slot] : -1;
    }
    __syncthreads();

    int lane = tid & 31, wid = tid >> 5;
    int wm = (wid & 1) * 16;
    int wn = (wid >> 1) * 32;
    const __nv_bfloat16* tok = g_tokb + (size_t)e * LP * C;

    float acc[4][4];
    #pragma unroll
    for (int ni = 0; ni < 4; ni++)
        #pragma unroll
        for (int q = 0; q < 4; q++) acc[ni][q] = 0.f;

    // load issue helper (stage s covers k0 = it*32)
    int ar = tid >> 2;              // 0..63 (only <32 used for A)
    int ac = (tid & 3) * 8;
    auto issue = [&](int it, int buf) {
        int k0 = it * 32;
        if (tid < 128) {
            int gi = sidx[ar];
            const void* src = (gi >= 0) ? (const void*)(g_xb + (size_t)gi * C + k0 + ac)
                                        : (const void*)g_xb;
            cp16z(&As[buf][ar][ac], src, gi >= 0);
        }
        #pragma unroll
        for (int i = 0; i < 2; i++) {
            int idx = tid + i * 256;
            int r = idx >> 2, c8 = (idx & 3) * 8;
            cp16(&Bs[buf][r][c8], tok + (size_t)r * C + k0 + c8);
        }
        CP_COMMIT();
    };

    issue(0, 0);
    for (int it = 0; it < 32; it++) {
        int buf = it & 1;
        if (it + 1 < 32) { issue(it + 1, buf ^ 1); CP_WAIT1(); }
        else CP_WAIT0();
        __syncthreads();
        #pragma unroll
        for (int ks = 0; ks < 32; ks += 16) {
            unsigned a[4], b[4][2];
            {
                unsigned addr = (unsigned)__cvta_generic_to_shared(
                    &As[buf][wm + (lane & 15)][ks + ((lane >> 4) << 3)]);
                asm volatile("ldmatrix.sync.aligned.m8n8.x4.shared.b16 {%0,%1,%2,%3}, [%4];"
                    : "=r"(a[0]), "=r"(a[1]), "=r"(a[2]), "=r"(a[3]) : "r"(addr));
            }
            #pragma unroll
            for (int nj = 0; nj < 2; nj++) {
                unsigned addr = (unsigned)__cvta_generic_to_shared(
                    &Bs[buf][wn + nj * 16 + ((lane >> 4) << 3) + (lane & 7)]
                        [ks + (((lane >> 3) & 1) << 3)]);
                asm volatile("ldmatrix.sync.aligned.m8n8.x4.shared.b16 {%0,%1,%2,%3}, [%4];"
                    : "=r"(b[nj * 2][0]), "=r"(b[nj * 2][1]),
                      "=r"(b[nj * 2 + 1][0]), "=r"(b[nj * 2 + 1][1]) : "r"(addr));
            }
            #pragma unroll
            for (int ni = 0; ni < 4; ni++)
                asm volatile(
                    "mma.sync.aligned.m16n8k16.row.col.f32.bf16.bf16.f32 "
                    "{%0,%1,%2,%3}, {%4,%5,%6,%7}, {%8,%9}, {%0,%1,%2,%3};"
                    : "+f"(acc[ni][0]), "+f"(acc[ni][1]), "+f"(acc[ni][2]), "+f"(acc[ni][3])
                    : "r"(a[0]), "r"(a[1]), "r"(a[2]), "r"(a[3]),
                      "r"(b[ni][0]), "r"(b[ni][1]));
        }
        __syncthreads();
    }

    // write S (scaled) to smem
    int grp = lane >> 2, qid = lane & 3;
    #pragma unroll
    for (int ni = 0; ni < 4; ni++) {
        S[wm + grp][wn + ni * 8 + qid * 2]         = acc[ni][0] * 0.03125f;
        S[wm + grp][wn + ni * 8 + qid * 2 + 1]     = acc[ni][1] * 0.03125f;
        S[wm + grp + 8][wn + ni * 8 + qid * 2]     = acc[ni][2] * 0.03125f;
        S[wm + grp + 8][wn + ni * 8 + qid * 2 + 1] = acc[ni][3] * 0.03125f;
    }
    __syncthreads();

    // softmax per row, store bf16
    for (int r = wid; r < 32; r += 8) {
        int token = sidx[r];
        float* row = S[r];
        float mx = -INFINITY;
        for (int l = lane; l < L; l += 32) mx = fmaxf(mx, row[l]);
        #pragma unroll
        for (int o = 16; o; o >>= 1) mx = fmaxf(mx, __shfl_xor_sync(0xffffffffu, mx, o));
        float sum = 0.f, v[4];
        #pragma unroll
        for (int q = 0; q < 4; q++) {
            int l = lane + q * 32;
            v[q] = (l < L) ? expf(row[l] - mx) : 0.f;
            sum += v[q];
        }
        #pragma unroll
        for (int o = 16; o; o >>= 1) sum += __shfl_xor_sync(0xffffffffu, sum, o);
        float inv = 1.f / sum;
        if (token >= 0) {
            #pragma unroll
            for (int q = 0; q < 4; q++) {
                int l = lane + q * 32;
                float w = (l >= 1 && l < L) ? v[q] * inv : 0.f;
                g_attnb[(size_t)token * LP + l] = __float2bfloat16(w);
            }
        }
    }
}

// ---------------------------------------------------------------------------
// Kernel 6: combine (bf16 HMMA). u = x + attn @ val_e^T.
// Per (expert, 128-token tile, 128-col chunk). K=128, two 64-steps.
// Warp: wm=(wid&3)*32, wn=(wid>>2)*64.
// ---------------------------------------------------------------------------
__global__ __launch_bounds__(256) void combine_kernel()
{
    int bx = blockIdx.x;
    int e = bx >> 9;
    int rem = bx & 511;
    int tile = rem >> 3;
    int n0 = (rem & 7) << 7;
    int cnt = g_cnt[e];
    if (tile * 128 >= cnt) return;

    __shared__ __nv_bfloat16 As[128][72];
    __shared__ __nv_bfloat16 Bs[128][72];
    __shared__ int sidx[128];

    int tid = threadIdx.x;
    if (tid < 128) {
        int slot = tile * 128 + tid;
        sidx[tid] = (slot < cnt) ? g_idx[e * NTOK + slot] : -1;
    }
    __syncthreads();

    int lane = tid & 31, wid = tid >> 5;
    int wm = (wid & 3) * 32;
    int wn = (wid >> 2) * 64;
    const __nv_bfloat16* val = g_valb + (size_t)e * C * LP;

    float acc[2][8][4];
    #pragma unroll
    for (int mi = 0; mi < 2; mi++)
        #pragma unroll
        for (int ni = 0; ni < 8; ni++)
            #pragma unroll
            for (int q = 0; q < 4; q++) acc[mi][ni][q] = 0.f;

    for (int k0 = 0; k0 < 128; k0 += 64) {
        #pragma unroll
        for (int i = 0; i < 4; i++) {
            int idx = tid + i * 256;
            int r = idx >> 3, c8 = (idx & 7) * 8;
            int gi = sidx[r];
            const void* srcA = (gi >= 0) ? (const void*)(g_attnb + (size_t)gi * LP + k0 + c8)
                                         : (const void*)g_attnb;
            cp16z(&As[r][c8], srcA, gi >= 0);
            cp16(&Bs[r][c8], val + (size_t)(n0 + r) * LP + k0 + c8);
        }
        CP_COMMIT();
        CP_WAIT0();
        __syncthreads();
        #pragma unroll
        for (int ks = 0; ks < 64; ks += 16) {
            unsigned a[2][4], b[8][2];
            #pragma unroll
            for (int mi = 0; mi < 2; mi++) {
                unsigned addr = (unsigned)__cvta_generic_to_shared(
                    &As[wm + mi * 16 + (lane & 15)][ks + ((lane >> 4) << 3)]);
                asm volatile("ldmatrix.sync.aligned.m8n8.x4.shared.b16 {%0,%1,%2,%3}, [%4];"
                    : "=r"(a[mi][0]), "=r"(a[mi][1]), "=r"(a[mi][2]), "=r"(a[mi][3])
                    : "r"(addr));
            }
            #pragma unroll
            for (int nj = 0; nj < 4; nj++) {
                unsigned addr = (unsigned)__cvta_generic_to_shared(
                    &Bs[wn + nj * 16 + ((lane >> 4) << 3) + (lane & 7)]
                        [ks + (((lane >> 3) & 1) << 3)]);
                asm volatile("ldmatrix.sync.aligned.m8n8.x4.shared.b16 {%0,%1,%2,%3}, [%4];"
                    : "=r"(b[nj * 2][0]), "=r"(b[nj * 2][1]),
                      "=r"(b[nj * 2 + 1][0]), "=r"(b[nj * 2 + 1][1]) : "r"(addr));
            }
            #pragma unroll
            for (int mi = 0; mi < 2; mi++)
                #pragma unroll
                for (int ni = 0; ni < 8; ni++)
                    asm volatile(
                        "mma.sync.aligned.m16n8k16.row.col.f32.bf16.bf16.f32 "
                        "{%0,%1,%2,%3}, {%4,%5,%6,%7}, {%8,%9}, {%0,%1,%2,%3};"
                        : "+f"(acc[mi][ni][0]), "+f"(acc[mi][ni][1]),
                          "+f"(acc[mi][ni][2]), "+f"(acc[mi][ni][3])
                        : "r"(a[mi][0]), "r"(a[mi][1]), "r"(a[mi][2]), "r"(a[mi][3]),
                          "r"(b[ni][0]), "r"(b[ni][1]));
        }
        __syncthreads();
    }

    int grp = lane >> 2, qid = lane & 3;
    #pragma unroll
    for (int mi = 0; mi < 2; mi++) {
        #pragma unroll
        for (int ni = 0; ni < 8; ni++) {
            #pragma unroll
            for (int half = 0; half < 2; half++) {
                int m = wm + mi * 16 + grp + half * 8;
                int gi = sidx[m];
                if (gi < 0) continue;
                int n = n0 + wn + ni * 8 + qid * 2;
                size_t xi = (size_t)gi * C + n;
                __nv_bfloat162 xv = *(const __nv_bfloat162*)(g_xb + xi);
                float u0 = __bfloat162float(xv.x) + acc[mi][ni][half * 2];
                float u1 = __bfloat162float(xv.y) + acc[mi][ni][half * 2 + 1];
                __nv_bfloat162 uv = __float22bfloat162_rn(make_float2(u0, u1));
                *(__nv_bfloat162*)(g_u + xi) = uv;
            }
        }
    }
}

// ---------------------------------------------------------------------------
// Kernel 7: final bf16 HMMA GEMM with cp.async 2-stage pipeline:
// out = feats + (u @ wd^T + bias)*scale. 128x128x32 tiles, grid (8, 64).
// ---------------------------------------------------------------------------
__global__ __launch_bounds__(256) void final_mma_kernel(
    const float* __restrict__ bias, const float* __restrict__ feats,
    const float* __restrict__ scale_p, float* __restrict__ out)
{
    __shared__ __nv_bfloat16 As[2][128][40];
    __shared__ __nv_bfloat16 Bs[2][128][40];

    int tid = threadIdx.x;
    int wid = tid >> 5, lane = tid & 31;
    int wm = (wid & 3) * 32;
    int wn = (wid >> 2) * 64;
    int bm0 = blockIdx.y * 128;
    int bn0 = blockIdx.x * 128;

    float acc[2][8][4];
    #pragma unroll
    for (int mi = 0; mi < 2; mi++)
        #pragma unroll
        for (int ni = 0; ni < 8; ni++)
            #pragma unroll
            for (int q = 0; q < 4; q++) acc[mi][ni][q] = 0.f;

    int lr = tid >> 2, lc = (tid & 3) * 8;
    auto issue = [&](int it, int buf) {
        int k0 = it * 32;
        #pragma unroll
        for (int i = 0; i < 2; i++) {
            int r = lr + i * 64;
            cp16(&As[buf][r][lc], g_u + (size_t)(bm0 + r) * C + k0 + lc);
            cp16(&Bs[buf][r][lc], g_wd + (size_t)(bn0 + r) * C + k0 + lc);
        }
        CP_COMMIT();
    };

    issue(0, 0);
    for (int it = 0; it < 32; it++) {
        int buf = it & 1;
        if (it + 1 < 32) { issue(it + 1, buf ^ 1); CP_WAIT1(); }
        else CP_WAIT0();
        __syncthreads();
        #pragma unroll
        for (int ks = 0; ks < 32; ks += 16) {
            unsigned a[2][4], b[8][2];
            #pragma unroll
            for (int mi = 0; mi < 2; mi++) {
                unsigned addr = (unsigned)__cvta_generic_to_shared(
                    &As[buf][wm + mi * 16 + (lane & 15)][ks + ((lane >> 4) << 3)]);
                asm volatile("ldmatrix.sync.aligned.m8n8.x4.shared.b16 {%0,%1,%2,%3}, [%4];"
                    : "=r"(a[mi][0]), "=r"(a[mi][1]), "=r"(a[mi][2]), "=r"(a[mi][3])
                    : "r"(addr));
            }
            #pragma unroll
            for (int nj = 0; nj < 4; nj++) {
                unsigned addr = (unsigned)__cvta_generic_to_shared(
                    &Bs[buf][wn + nj * 16 + ((lane >> 4) << 3) + (lane & 7)]
                        [ks + (((lane >> 3) & 1) << 3)]);
                asm volatile("ldmatrix.sync.aligned.m8n8.x4.shared.b16 {%0,%1,%2,%3}, [%4];"
                    : "=r"(b[nj * 2][0]), "=r"(b[nj * 2][1]),
                      "=r"(b[nj * 2 + 1][0]), "=r"(b[nj * 2 + 1][1]) : "r"(addr));
            }
            #pragma unroll
            for (int mi = 0; mi < 2; mi++)
                #pragma unroll
                for (int ni = 0; ni < 8; ni++)
                    asm volatile(
                        "mma.sync.aligned.m16n8k16.row.col.f32.bf16.bf16.f32 "
                        "{%0,%1,%2,%3}, {%4,%5,%6,%7}, {%8,%9}, {%0,%1,%2,%3};"
                        : "+f"(acc[mi][ni][0]), "+f"(acc[mi][ni][1]),
                          "+f"(acc[mi][ni][2]), "+f"(acc[mi][ni][3])
                        : "r"(a[mi][0]), "r"(a[mi][1]), "r"(a[mi][2]), "r"(a[mi][3]),
                          "r"(b[ni][0]), "r"(b[ni][1]));
        }
        __syncthreads();
    }

    float sc = scale_p[0];
    int grp = lane >> 2, qid = lane & 3;
    #pragma unroll
    for (int mi = 0; mi < 2; mi++) {
        #pragma unroll
        for (int ni = 0; ni < 8; ni++) {
            int m = bm0 + wm + mi * 16 + grp;
            int n = bn0 + wn + ni * 8 + qid * 2;
            size_t i0 = (size_t)m * C + n;
            size_t i1 = (size_t)(m + 8) * C + n;
            float b0 = bias[n], b1 = bias[n + 1];
            out[i0]     = feats[i0]     + (acc[mi][ni][0] + b0) * sc;
            out[i0 + 1] = feats[i0 + 1] + (acc[mi][ni][1] + b1) * sc;
            out[i1]     = feats[i1]     + (acc[mi][ni][2] + b0) * sc;
            out[i1 + 1] = feats[i1 + 1] + (acc[mi][ni][3] + b1) * sc;
        }
    }
}

// ---------------------------------------------------------------------------
// Launch. Inputs: 0 feats, 1 A, 2 B, 3 w_gate, 4 wt_w, 5 wt_b, 6 wd_w,
//                 7 wd_b, 8 scale
// ---------------------------------------------------------------------------
extern "C" void kernel_launch(void* const* d_in, const int* in_sizes, int n_in,
                              void* d_out, int out_size)
{
    const float* feats  = (const float*)d_in[0];
    const float* A      = (const float*)d_in[1];
    const float* Bm     = (const float*)d_in[2];
    const float* w_gate = (const float*)d_in[3];
    const float* wt_w   = (const float*)d_in[4];
    const float* wt_b   = (const float*)d_in[5];
    const float* wd_w   = (const float*)d_in[6];
    const float* wd_b   = (const float*)d_in[7];
    const float* scale  = (const float*)d_in[8];
    float* out = (float*)d_out;

    int* cnt_p; cudaGetSymbolAddress((void**)&cnt_p, g_cnt);
    cudaMemsetAsync(cnt_p, 0, E * sizeof(int));

    conv_gate_kernel<<<NTOK / 8, 256>>>(feats, w_gate);
    tokens_kernel<<<E * 128, 256>>>(A, Bm);
    val_gemm_kernel<<<dim3(16, 2, E), 256>>>(wt_w, wt_b);
    conv_wd_kernel<<<1024, 256>>>(wd_w);
    attn_kernel<<<E * 256, 256>>>();
    combine_kernel<<<E * 64 * 8, 256>>>();
    final_mma_kernel<<<dim3(8, 64), 256>>>(wd_b, feats, scale, out);
}

// round 4
// speedup vs baseline: 3.9051x; 1.0876x over previous
#include <cuda_runtime.h>
#include <cuda_bf16.h>
#include <math.h>

#define NTOK 8192
#define C    1024
#define E    6
#define L    100
#define LP   128      // L padded

// Scratch
__device__ float g_tokens[E * L * C];                 // fp32 tokens [e][l][c]
__device__ __nv_bfloat16 g_tokb[E * LP * C];          // bf16 tokens, L-padded
__device__ __nv_bfloat16 g_valb[E * C * LP];          // bf16 val, TRANSPOSED [e][c][l]
__device__ __nv_bfloat16 g_xb[NTOK * C];              // bf16 feats
__device__ __nv_bfloat16 g_u[NTOK * C];               // bf16 u = x + delta_f
__device__ __nv_bfloat16 g_wd[C * C];                 // bf16 wd_w
__device__ int g_idx[E * NTOK];
__device__ int g_cnt[E];

// ---------------------------------------------------------------------------
// cp.async helpers
// ---------------------------------------------------------------------------
__device__ __forceinline__ void cp16(void* smem, const void* gmem) {
    unsigned s = (unsigned)__cvta_generic_to_shared(smem);
    asm volatile("cp.async.cg.shared.global [%0], [%1], 16;\n" :: "r"(s), "l"(gmem));
}
__device__ __forceinline__ void cp16z(void* smem, const void* gmem, bool valid) {
    unsigned s = (unsigned)__cvta_generic_to_shared(smem);
    int sz = valid ? 16 : 0;
    asm volatile("cp.async.cg.shared.global [%0], [%1], 16, %2;\n" :: "r"(s), "l"(gmem), "r"(sz));
}
#define CP_COMMIT() asm volatile("cp.async.commit_group;\n")
#define CP_WAIT2()  asm volatile("cp.async.wait_group 2;\n")
#define CP_WAIT1()  asm volatile("cp.async.wait_group 1;\n")
#define CP_WAIT0()  asm volatile("cp.async.wait_group 0;\n")

// ---------------------------------------------------------------------------
// Kernel 1: fused feats->bf16 conversion + gating (fp32 logits, exact argmax)
// ---------------------------------------------------------------------------
__global__ __launch_bounds__(256) void conv_gate_kernel(
    const float* __restrict__ feats, const float* __restrict__ w_gate)
{
    __shared__ float sw[E * C];
    int tid = threadIdx.x;
    for (int i = tid; i < E * C; i += 256) {
        int e = i >> 10, c = i & 1023;
        sw[i] = w_gate[c * E + e];
    }
    __syncthreads();
    int lane = tid & 31, wid = tid >> 5;
    int t = blockIdx.x * 8 + wid;
    const float* x = feats + (size_t)t * C;
    __nv_bfloat16* xb = g_xb + (size_t)t * C;

    float acc[E];
    #pragma unroll
    for (int e = 0; e < E; e++) acc[e] = 0.f;

    #pragma unroll
    for (int i = 0; i < 8; i++) {
        int c0 = 4 * (lane + 32 * i);
        float4 v = *(const float4*)(x + c0);
        __nv_bfloat162 h0 = __float22bfloat162_rn(make_float2(v.x, v.y));
        __nv_bfloat162 h1 = __float22bfloat162_rn(make_float2(v.z, v.w));
        uint2 p; p.x = *(unsigned*)&h0; p.y = *(unsigned*)&h1;
        *(uint2*)(xb + c0) = p;
        #pragma unroll
        for (int e = 0; e < E; e++) {
            float4 w = *(const float4*)&sw[e * C + c0];
            acc[e] += v.x * w.x + v.y * w.y + v.z * w.z + v.w * w.w;
        }
    }
    #pragma unroll
    for (int e = 0; e < E; e++)
        #pragma unroll
        for (int o = 16; o; o >>= 1) acc[e] += __shfl_xor_sync(0xffffffffu, acc[e], o);
    if (lane == 0) {
        int best = 0; float bv = acc[0];
        #pragma unroll
        for (int e = 1; e < E; e++)
            if (acc[e] > bv) { bv = acc[e]; best = e; }
        int pos = atomicAdd(&g_cnt[best], 1);
        g_idx[best * NTOK + pos] = t;
    }
}

// ---------------------------------------------------------------------------
// Kernel 2: tokens[e,l,c] = sum_r A[e,l,r]*B[e,r,c]; fp32 + bf16(padded) out.
// ---------------------------------------------------------------------------
__global__ __launch_bounds__(256) void tokens_kernel(
    const float* __restrict__ A, const float* __restrict__ Bm)
{
    int b = blockIdx.x;
    int e = b >> 7, l = b & 127;
    int tid = threadIdx.x;
    if (l >= L) {
        __nv_bfloat16 z = __float2bfloat16(0.f);
        #pragma unroll
        for (int i = 0; i < 4; i++)
            g_tokb[((size_t)(e * LP + l)) * C + tid + 256 * i] = z;
        return;
    }
    __shared__ float sa[16];
    if (tid < 16) sa[tid] = A[(e * L + l) * 16 + tid];
    __syncthreads();
    const float* Bp = Bm + (size_t)e * 16 * C;
    #pragma unroll
    for (int i = 0; i < 4; i++) {
        int c = tid + 256 * i;
        float acc = 0.f;
        #pragma unroll
        for (int r = 0; r < 16; r++) acc += sa[r] * Bp[r * C + c];
        g_tokens[((size_t)(e * L + l)) * C + c] = acc;
        g_tokb[((size_t)(e * LP + l)) * C + c] = __float2bfloat16(acc);
    }
}

// ---------------------------------------------------------------------------
// Kernel 3: val = tokens @ wt_w^T + wt_b -> bf16 TRANSPOSED [e][n][l]
// ---------------------------------------------------------------------------
__global__ __launch_bounds__(256) void val_gemm_kernel(
    const float* __restrict__ W, const float* __restrict__ bias)
{
    __shared__ float As[16][68];
    __shared__ float Bs[16][68];
    int e = blockIdx.z;
    const float* Amat = g_tokens + (size_t)e * L * C;
    int tid = threadIdx.x;
    int bm0 = blockIdx.y * 64;
    int bn0 = blockIdx.x * 64;
    int ty = tid >> 4, tx = tid & 15;
    int lr = tid >> 2, lk = (tid & 3) << 2;

    float acc[4][4];
    #pragma unroll
    for (int i = 0; i < 4; i++)
        #pragma unroll
        for (int j = 0; j < 4; j++) acc[i][j] = 0.f;

    for (int k0 = 0; k0 < C; k0 += 16) {
        int gm = bm0 + lr;
        float4 va = make_float4(0.f, 0.f, 0.f, 0.f);
        if (gm < L) va = *(const float4*)(Amat + (size_t)gm * C + k0 + lk);
        As[lk + 0][lr] = va.x; As[lk + 1][lr] = va.y;
        As[lk + 2][lr] = va.z; As[lk + 3][lr] = va.w;
        float4 vb = *(const float4*)(W + (size_t)(bn0 + lr) * C + k0 + lk);
        Bs[lk + 0][lr] = vb.x; Bs[lk + 1][lr] = vb.y;
        Bs[lk + 2][lr] = vb.z; Bs[lk + 3][lr] = vb.w;
        __syncthreads();
        #pragma unroll
        for (int kk = 0; kk < 16; kk++) {
            float4 a = *(float4*)&As[kk][ty * 4];
            float4 b = *(float4*)&Bs[kk][tx * 4];
            float af[4] = {a.x, a.y, a.z, a.w};
            float bf[4] = {b.x, b.y, b.z, b.w};
            #pragma unroll
            for (int i = 0; i < 4; i++)
                #pragma unroll
                for (int j = 0; j < 4; j++) acc[i][j] += af[i] * bf[j];
        }
        __syncthreads();
    }
    #pragma unroll
    for (int i = 0; i < 4; i++) {
        int l = bm0 + ty * 4 + i;
        #pragma unroll
        for (int j = 0; j < 4; j++) {
            int n = bn0 + tx * 4 + j;
            float v = (l < L) ? acc[i][j] + bias[n] : 0.f;
            g_valb[((size_t)e * C + n) * LP + l] = __float2bfloat16(v);
        }
    }
}

// ---------------------------------------------------------------------------
// Kernel 4: wd_w -> bf16
// ---------------------------------------------------------------------------
__global__ __launch_bounds__(256) void conv_wd_kernel(const float* __restrict__ W)
{
    int idx = blockIdx.x * 256 + threadIdx.x;
    float4 v = *(const float4*)(W + (size_t)idx * 4);
    __nv_bfloat162 h0 = __float22bfloat162_rn(make_float2(v.x, v.y));
    __nv_bfloat162 h1 = __float22bfloat162_rn(make_float2(v.z, v.w));
    uint2 p; p.x = *(unsigned*)&h0; p.y = *(unsigned*)&h1;
    *(uint2*)(g_wd + (size_t)idx * 4) = p;
}

// ---------------------------------------------------------------------------
// Kernel 5: FUSED attn + combine. Per (expert, 32-token tile):
//  Phase A: S = Xg @ tok_e^T / 32 (HMMA, 3-slot/2-deep cp.async, 1 sync/iter)
//  softmax -> bf16 P[32][128] in smem (l=0, l>=100 zeroed)
//  Phase B: u = x + P @ val_e^T over 8 chunks of 128 cols (HMMA, 2-slot)
// Dynamic smem layout (bytes):
//  [0, 69632):  union { phase A: As[3][32][40] + Bs[3][128][40] (38400);
//                       phase B: Vs[2][128][136] (69632) }
//  [69632, 86528): S fp32 [32][132]
//  [86528, 95232): P bf16 [32][136]
//  [95232, 95360): sidx[32]
// ---------------------------------------------------------------------------
#define FUS_SMEM 95360
#define AS_A(s,r,c) (*(__nv_bfloat16*)(dyn + (((s)*32*40 + (r)*40 + (c)) << 1)))
#define BS_A(s,r,c) (*(__nv_bfloat16*)(dyn + 7680 + (((s)*128*40 + (r)*40 + (c)) << 1)))
#define VS_B(s,r,c) (*(__nv_bfloat16*)(dyn + (((s)*128*136 + (r)*136 + (c)) << 1)))
#define S_AT(r,c)   (*(float*)(dyn + 69632 + (((r)*132 + (c)) << 2)))
#define P_AT(r,c)   (*(__nv_bfloat16*)(dyn + 86528 + (((r)*136 + (c)) << 1)))
#define SIDX(i)     (*(int*)(dyn + 95232 + ((i) << 2)))

__global__ __launch_bounds__(256) void fused_attn_combine_kernel()
{
    extern __shared__ char dyn[];
    int e = blockIdx.x >> 8;
    int tile = blockIdx.x & 255;
    int cnt = g_cnt[e];
    if (tile * 32 >= cnt) return;

    int tid = threadIdx.x;
    if (tid < 32) {
        int slot = tile * 32 + tid;
        SIDX(tid) = (slot < cnt) ? g_idx[e * NTOK + slot] : -1;
    }
    __syncthreads();

    int lane = tid & 31, wid = tid >> 5;
    const __nv_bfloat16* tok = g_tokb + (size_t)e * LP * C;
    const __nv_bfloat16* val = g_valb + (size_t)e * C * LP;

    // ---------------- Phase A ----------------
    int wmA = (wid & 1) * 16;
    int wnA = (wid >> 1) * 32;

    float accA[4][4];
    #pragma unroll
    for (int ni = 0; ni < 4; ni++)
        #pragma unroll
        for (int q = 0; q < 4; q++) accA[ni][q] = 0.f;

    int ar = tid >> 2;
    int ac = (tid & 3) * 8;
    auto issueA = [&](int it, int s) {
        int k0 = it * 32;
        if (tid < 128) {
            int gi = SIDX(ar);
            const void* src = (gi >= 0) ? (const void*)(g_xb + (size_t)gi * C + k0 + ac)
                                        : (const void*)g_xb;
            cp16z(&AS_A(s, ar, ac), src, gi >= 0);
        }
        #pragma unroll
        for (int i = 0; i < 2; i++) {
            int idx = tid + i * 256;
            int r = idx >> 2, c8 = (idx & 3) * 8;
            cp16(&BS_A(s, r, c8), tok + (size_t)r * C + k0 + c8);
        }
        CP_COMMIT();
    };

    issueA(0, 0); issueA(1, 1);
    for (int it = 0; it < 32; it++) {
        int s = it % 3;
        if (it < 31) CP_WAIT1(); else CP_WAIT0();
        __syncthreads();
        if (it + 2 < 32) issueA(it + 2, (it + 2) % 3);
        #pragma unroll
        for (int ks = 0; ks < 32; ks += 16) {
            unsigned a[4], b[4][2];
            {
                unsigned addr = (unsigned)__cvta_generic_to_shared(
                    &AS_A(s, wmA + (lane & 15), ks + ((lane >> 4) << 3)));
                asm volatile("ldmatrix.sync.aligned.m8n8.x4.shared.b16 {%0,%1,%2,%3}, [%4];"
                    : "=r"(a[0]), "=r"(a[1]), "=r"(a[2]), "=r"(a[3]) : "r"(addr));
            }
            #pragma unroll
            for (int nj = 0; nj < 2; nj++) {
                unsigned addr = (unsigned)__cvta_generic_to_shared(
                    &BS_A(s, wnA + nj * 16 + ((lane >> 4) << 3) + (lane & 7),
                          ks + (((lane >> 3) & 1) << 3)));
                asm volatile("ldmatrix.sync.aligned.m8n8.x4.shared.b16 {%0,%1,%2,%3}, [%4];"
                    : "=r"(b[nj * 2][0]), "=r"(b[nj * 2][1]),
                      "=r"(b[nj * 2 + 1][0]), "=r"(b[nj * 2 + 1][1]) : "r"(addr));
            }
            #pragma unroll
            for (int ni = 0; ni < 4; ni++)
                asm volatile(
                    "mma.sync.aligned.m16n8k16.row.col.f32.bf16.bf16.f32 "
                    "{%0,%1,%2,%3}, {%4,%5,%6,%7}, {%8,%9}, {%0,%1,%2,%3};"
                    : "+f"(accA[ni][0]), "+f"(accA[ni][1]), "+f"(accA[ni][2]), "+f"(accA[ni][3])
                    : "r"(a[0]), "r"(a[1]), "r"(a[2]), "r"(a[3]),
                      "r"(b[ni][0]), "r"(b[ni][1]));
        }
    }

    // write S (scaled) to smem
    int grp = lane >> 2, qid = lane & 3;
    #pragma unroll
    for (int ni = 0; ni < 4; ni++) {
        S_AT(wmA + grp,     wnA + ni * 8 + qid * 2)     = accA[ni][0] * 0.03125f;
        S_AT(wmA + grp,     wnA + ni * 8 + qid * 2 + 1) = accA[ni][1] * 0.03125f;
        S_AT(wmA + grp + 8, wnA + ni * 8 + qid * 2)     = accA[ni][2] * 0.03125f;
        S_AT(wmA + grp + 8, wnA + ni * 8 + qid * 2 + 1) = accA[ni][3] * 0.03125f;
    }
    __syncthreads();   // S complete; all phase A smem reads done

    // prefetch first two val chunks into Vs (overlaps softmax)
    auto issueV = [&](int nc, int s) {
        #pragma unroll
        for (int i = 0; i < 8; i++) {
            int idx = tid + i * 256;             // 0..2047
            int r = idx >> 4;                    // 0..127
            int c8 = (idx & 15) * 8;             // 0..120
            cp16(&VS_B(s, r, c8), val + (size_t)(nc * 128 + r) * LP + c8);
        }
        CP_COMMIT();
    };
    issueV(0, 0);
    issueV(1, 1);

    // softmax per row -> P bf16
    for (int r = wid; r < 32; r += 8) {
        float mx = -INFINITY;
        for (int l = lane; l < L; l += 32) mx = fmaxf(mx, S_AT(r, l));
        #pragma unroll
        for (int o = 16; o; o >>= 1) mx = fmaxf(mx, __shfl_xor_sync(0xffffffffu, mx, o));
        float sum = 0.f, v[4];
        #pragma unroll
        for (int q = 0; q < 4; q++) {
            int l = lane + q * 32;
            v[q] = (l < L) ? expf(S_AT(r, l) - mx) : 0.f;
            sum += v[q];
        }
        #pragma unroll
        for (int o = 16; o; o >>= 1) sum += __shfl_xor_sync(0xffffffffu, sum, o);
        float inv = 1.f / sum;
        #pragma unroll
        for (int q = 0; q < 4; q++) {
            int l = lane + q * 32;
            float w = (l >= 1 && l < L) ? v[q] * inv : 0.f;
            P_AT(r, l) = __float2bfloat16(w);
        }
    }
    __syncthreads();   // P ready

    // ---------------- Phase B ----------------
    // warp wid handles 16 cols of each 128-col chunk
    for (int nc = 0; nc < 8; nc++) {
        int s = nc & 1;
        if (nc < 7) CP_WAIT1(); else CP_WAIT0();
        __syncthreads();

        float accB[2][2][4];
        #pragma unroll
        for (int mi = 0; mi < 2; mi++)
            #pragma unroll
            for (int ni = 0; ni < 2; ni++)
                #pragma unroll
                for (int q = 0; q < 4; q++) accB[mi][ni][q] = 0.f;

        #pragma unroll
        for (int ks = 0; ks < 128; ks += 16) {
            unsigned a[2][4], b[2][2];
            #pragma unroll
            for (int mi = 0; mi < 2; mi++) {
                unsigned addr = (unsigned)__cvta_generic_to_shared(
                    &P_AT(mi * 16 + (lane & 15), ks + ((lane >> 4) << 3)));
                asm volatile("ldmatrix.sync.aligned.m8n8.x4.shared.b16 {%0,%1,%2,%3}, [%4];"
                    : "=r"(a[mi][0]), "=r"(a[mi][1]), "=r"(a[mi][2]), "=r"(a[mi][3])
                    : "r"(addr));
            }
            {
                unsigned addr = (unsigned)__cvta_generic_to_shared(
                    &VS_B(s, wid * 16 + ((lane >> 4) << 3) + (lane & 7),
                          ks + (((lane >> 3) & 1) << 3)));
                asm volatile("ldmatrix.sync.aligned.m8n8.x4.shared.b16 {%0,%1,%2,%3}, [%4];"
                    : "=r"(b[0][0]), "=r"(b[0][1]), "=r"(b[1][0]), "=r"(b[1][1])
                    : "r"(addr));
            }
            #pragma unroll
            for (int mi = 0; mi < 2; mi++)
                #pragma unroll
                for (int ni = 0; ni < 2; ni++)
                    asm volatile(
                        "mma.sync.aligned.m16n8k16.row.col.f32.bf16.bf16.f32 "
                        "{%0,%1,%2,%3}, {%4,%5,%6,%7}, {%8,%9}, {%0,%1,%2,%3};"
                        : "+f"(accB[mi][ni][0]), "+f"(accB[mi][ni][1]),
                          "+f"(accB[mi][ni][2]), "+f"(accB[mi][ni][3])
                        : "r"(a[mi][0]), "r"(a[mi][1]), "r"(a[mi][2]), "r"(a[mi][3]),
                          "r"(b[ni][0]), "r"(b[ni][1]));
        }
        __syncthreads();
        if (nc + 2 < 8) issueV(nc + 2, s);

        // epilogue: u = x + accB, store by token id
        #pragma unroll
        for (int mi = 0; mi < 2; mi++) {
            #pragma unroll
            for (int ni = 0; ni < 2; ni++) {
                #pragma unroll
                for (int half = 0; half < 2; half++) {
                    int m = mi * 16 + grp + half * 8;
                    int gi = SIDX(m);
                    if (gi < 0) continue;
                    int n = nc * 128 + wid * 16 + ni * 8 + qid * 2;
                    size_t xi = (size_t)gi * C + n;
                    __nv_bfloat162 xv = *(const __nv_bfloat162*)(g_xb + xi);
                    float u0 = __bfloat162float(xv.x) + accB[mi][ni][half * 2];
                    float u1 = __bfloat162float(xv.y) + accB[mi][ni][half * 2 + 1];
                    __nv_bfloat162 uv = __float22bfloat162_rn(make_float2(u0, u1));
                    *(__nv_bfloat162*)(g_u + xi) = uv;
                }
            }
        }
    }
}

// ---------------------------------------------------------------------------
// Kernel 6: final bf16 HMMA GEMM, 4-stage/3-deep cp.async, 1 sync per k-iter:
// out = feats + (u @ wd^T + bias)*scale. 128x128x32 tiles, grid (8, 64).
// Dynamic smem: As[4][128][40] (40960B) + Bs[4][128][40] (40960B) = 81920B.
// ---------------------------------------------------------------------------
#define FIN_SMEM 81920
#define AS_F(s,r,c) (*(__nv_bfloat16*)(dyn + (((s)*128*40 + (r)*40 + (c)) << 1)))
#define BS_F(s,r,c) (*(__nv_bfloat16*)(dyn + 40960 + (((s)*128*40 + (r)*40 + (c)) << 1)))

__global__ __launch_bounds__(256) void final_mma_kernel(
    const float* __restrict__ bias, const float* __restrict__ feats,
    const float* __restrict__ scale_p, float* __restrict__ out)
{
    extern __shared__ char dyn[];
    int tid = threadIdx.x;
    int wid = tid >> 5, lane = tid & 31;
    int wm = (wid & 3) * 32;
    int wn = (wid >> 2) * 64;
    int bm0 = blockIdx.y * 128;
    int bn0 = blockIdx.x * 128;

    float acc[2][8][4];
    #pragma unroll
    for (int mi = 0; mi < 2; mi++)
        #pragma unroll
        for (int ni = 0; ni < 8; ni++)
            #pragma unroll
            for (int q = 0; q < 4; q++) acc[mi][ni][q] = 0.f;

    int lr = tid >> 2, lc = (tid & 3) * 8;
    auto issue = [&](int it, int s) {
        int k0 = it * 32;
        #pragma unroll
        for (int i = 0; i < 2; i++) {
            int r = lr + i * 64;
            cp16(&AS_F(s, r, lc), g_u + (size_t)(bm0 + r) * C + k0 + lc);
            cp16(&BS_F(s, r, lc), g_wd + (size_t)(bn0 + r) * C + k0 + lc);
        }
        CP_COMMIT();
    };

    issue(0, 0); issue(1, 1); issue(2, 2);
    for (int it = 0; it < 32; it++) {
        int s = it & 3;
        if (it < 30) CP_WAIT2();
        else if (it == 30) CP_WAIT1();
        else CP_WAIT0();
        __syncthreads();
        if (it + 3 < 32) issue(it + 3, (it + 3) & 3);
        #pragma unroll
        for (int ks = 0; ks < 32; ks += 16) {
            unsigned a[2][4], b[8][2];
            #pragma unroll
            for (int mi = 0; mi < 2; mi++) {
                unsigned addr = (unsigned)__cvta_generic_to_shared(
                    &AS_F(s, wm + mi * 16 + (lane & 15), ks + ((lane >> 4) << 3)));
                asm volatile("ldmatrix.sync.aligned.m8n8.x4.shared.b16 {%0,%1,%2,%3}, [%4];"
                    : "=r"(a[mi][0]), "=r"(a[mi][1]), "=r"(a[mi][2]), "=r"(a[mi][3])
                    : "r"(addr));
            }
            #pragma unroll
            for (int nj = 0; nj < 4; nj++) {
                unsigned addr = (unsigned)__cvta_generic_to_shared(
                    &BS_F(s, wn + nj * 16 + ((lane >> 4) << 3) + (lane & 7),
                          ks + (((lane >> 3) & 1) << 3)));
                asm volatile("ldmatrix.sync.aligned.m8n8.x4.shared.b16 {%0,%1,%2,%3}, [%4];"
                    : "=r"(b[nj * 2][0]), "=r"(b[nj * 2][1]),
                      "=r"(b[nj * 2 + 1][0]), "=r"(b[nj * 2 + 1][1]) : "r"(addr));
            }
            #pragma unroll
            for (int mi = 0; mi < 2; mi++)
                #pragma unroll
                for (int ni = 0; ni < 8; ni++)
                    asm volatile(
                        "mma.sync.aligned.m16n8k16.row.col.f32.bf16.bf16.f32 "
                        "{%0,%1,%2,%3}, {%4,%5,%6,%7}, {%8,%9}, {%0,%1,%2,%3};"
                        : "+f"(acc[mi][ni][0]), "+f"(acc[mi][ni][1]),
                          "+f"(acc[mi][ni][2]), "+f"(acc[mi][ni][3])
                        : "r"(a[mi][0]), "r"(a[mi][1]), "r"(a[mi][2]), "r"(a[mi][3]),
                          "r"(b[ni][0]), "r"(b[ni][1]));
        }
    }

    float sc = scale_p[0];
    int grp = lane >> 2, qid = lane & 3;
    #pragma unroll
    for (int mi = 0; mi < 2; mi++) {
        #pragma unroll
        for (int ni = 0; ni < 8; ni++) {
            int m = bm0 + wm + mi * 16 + grp;
            int n = bn0 + wn + ni * 8 + qid * 2;
            size_t i0 = (size_t)m * C + n;
            size_t i1 = (size_t)(m + 8) * C + n;
            float b0 = bias[n], b1 = bias[n + 1];
            out[i0]     = feats[i0]     + (acc[mi][ni][0] + b0) * sc;
            out[i0 + 1] = feats[i0 + 1] + (acc[mi][ni][1] + b1) * sc;
            out[i1]     = feats[i1]     + (acc[mi][ni][2] + b0) * sc;
            out[i1 + 1] = feats[i1 + 1] + (acc[mi][ni][3] + b1) * sc;
        }
    }
}

// ---------------------------------------------------------------------------
// Launch. Inputs: 0 feats, 1 A, 2 B, 3 w_gate, 4 wt_w, 5 wt_b, 6 wd_w,
//                 7 wd_b, 8 scale
// ---------------------------------------------------------------------------
extern "C" void kernel_launch(void* const* d_in, const int* in_sizes, int n_in,
                              void* d_out, int out_size)
{
    const float* feats  = (const float*)d_in[0];
    const float* A      = (const float*)d_in[1];
    const float* Bm     = (const float*)d_in[2];
    const float* w_gate = (const float*)d_in[3];
    const float* wt_w   = (const float*)d_in[4];
    const float* wt_b   = (const float*)d_in[5];
    const float* wd_w   = (const float*)d_in[6];
    const float* wd_b   = (const float*)d_in[7];
    const float* scale  = (const float*)d_in[8];
    float* out = (float*)d_out;

    cudaFuncSetAttribute(fused_attn_combine_kernel,
                         cudaFuncAttributeMaxDynamicSharedMemorySize, FUS_SMEM);
    cudaFuncSetAttribute(final_mma_kernel,
                         cudaFuncAttributeMaxDynamicSharedMemorySize, FIN_SMEM);

    int* cnt_p; cudaGetSymbolAddress((void**)&cnt_p, g_cnt);
    cudaMemsetAsync(cnt_p, 0, E * sizeof(int));

    conv_gate_kernel<<<NTOK / 8, 256>>>(feats, w_gate);
    tokens_kernel<<<E * 128, 256>>>(A, Bm);
    val_gemm_kernel<<<dim3(16, 2, E), 256>>>(wt_w, wt_b);
    conv_wd_kernel<<<1024, 256>>>(wd_w);
    fused_attn_combine_kernel<<<E * 256, 256, FUS_SMEM>>>();
    final_mma_kernel<<<dim3(8, 64), 256, FIN_SMEM>>>(wd_b, feats, scale, out);
}

// round 7
// speedup vs baseline: 4.3690x; 1.1188x over previous
#include <cuda_runtime.h>
#include <cuda_bf16.h>
#include <math.h>
#include <cstdint>

#define NTOK 8192
#define C    1024
#define E    6
#define L    100
#define LP   128      // L padded

// int8 quantization scales for the final GEMM
#define SU_Q 24.0f
#define SW_Q 800.0f
#define INV_Q (1.0f / (24.0f * 800.0f))

// Scratch
__device__ float g_tokens[E * L * C];                 // fp32 tokens [e][l][c]
__device__ __nv_bfloat16 g_tokb[E * LP * C];          // bf16 tokens, L-padded
__device__ __nv_bfloat16 g_valb[E * C * LP];          // bf16 val, TRANSPOSED [e][c][l]
__device__ __nv_bfloat16 g_xb[NTOK * C];              // bf16 feats
__device__ int8_t g_u8[NTOK * C];                     // s8 u = x + delta_f (x SU_Q)
__device__ int8_t g_wd8[C * C];                       // s8 wd_w (x SW_Q)
__device__ int g_idx[E * NTOK];
__device__ int g_cnt[E];

// ---------------------------------------------------------------------------
// cp.async helpers
// ---------------------------------------------------------------------------
__device__ __forceinline__ void cp16(void* smem, const void* gmem) {
    unsigned s = (unsigned)__cvta_generic_to_shared(smem);
    asm volatile("cp.async.cg.shared.global [%0], [%1], 16;\n" :: "r"(s), "l"(gmem));
}
__device__ __forceinline__ void cp16z(void* smem, const void* gmem, bool valid) {
    unsigned s = (unsigned)__cvta_generic_to_shared(smem);
    int sz = valid ? 16 : 0;
    asm volatile("cp.async.cg.shared.global [%0], [%1], 16, %2;\n" :: "r"(s), "l"(gmem), "r"(sz));
}
#define CP_COMMIT() asm volatile("cp.async.commit_group;\n")
#define CP_WAIT2()  asm volatile("cp.async.wait_group 2;\n")
#define CP_WAIT1()  asm volatile("cp.async.wait_group 1;\n")
#define CP_WAIT0()  asm volatile("cp.async.wait_group 0;\n")

__device__ __forceinline__ int clamp127(int v) {
    return v > 127 ? 127 : (v < -127 ? -127 : v);
}

// ---------------------------------------------------------------------------
// Kernel 1: fused feats->bf16 conversion + gating (fp32 logits, exact argmax)
// ---------------------------------------------------------------------------
__global__ __launch_bounds__(256) void conv_gate_kernel(
    const float* __restrict__ feats, const float* __restrict__ w_gate)
{
    __shared__ float sw[E * C];
    int tid = threadIdx.x;
    for (int i = tid; i < E * C; i += 256) {
        int e = i >> 10, c = i & 1023;
        sw[i] = w_gate[c * E + e];
    }
    __syncthreads();
    int lane = tid & 31, wid = tid >> 5;
    int t = blockIdx.x * 8 + wid;
    const float* x = feats + (size_t)t * C;
    __nv_bfloat16* xb = g_xb + (size_t)t * C;

    float acc[E];
    #pragma unroll
    for (int e = 0; e < E; e++) acc[e] = 0.f;

    #pragma unroll
    for (int i = 0; i < 8; i++) {
        int c0 = 4 * (lane + 32 * i);
        float4 v = *(const float4*)(x + c0);
        __nv_bfloat162 h0 = __float22bfloat162_rn(make_float2(v.x, v.y));
        __nv_bfloat162 h1 = __float22bfloat162_rn(make_float2(v.z, v.w));
        uint2 p; p.x = *(unsigned*)&h0; p.y = *(unsigned*)&h1;
        *(uint2*)(xb + c0) = p;
        #pragma unroll
        for (int e = 0; e < E; e++) {
            float4 w = *(const float4*)&sw[e * C + c0];
            acc[e] += v.x * w.x + v.y * w.y + v.z * w.z + v.w * w.w;
        }
    }
    #pragma unroll
    for (int e = 0; e < E; e++)
        #pragma unroll
        for (int o = 16; o; o >>= 1) acc[e] += __shfl_xor_sync(0xffffffffu, acc[e], o);
    if (lane == 0) {
        int best = 0; float bv = acc[0];
        #pragma unroll
        for (int e = 1; e < E; e++)
            if (acc[e] > bv) { bv = acc[e]; best = e; }
        int pos = atomicAdd(&g_cnt[best], 1);
        g_idx[best * NTOK + pos] = t;
    }
}

// ---------------------------------------------------------------------------
// Kernel 2: tokens[e,l,c] = sum_r A[e,l,r]*B[e,r,c]; fp32 + bf16(padded) out.
// ---------------------------------------------------------------------------
__global__ __launch_bounds__(256) void tokens_kernel(
    const float* __restrict__ A, const float* __restrict__ Bm)
{
    int b = blockIdx.x;
    int e = b >> 7, l = b & 127;
    int tid = threadIdx.x;
    if (l >= L) {
        __nv_bfloat16 z = __float2bfloat16(0.f);
        #pragma unroll
        for (int i = 0; i < 4; i++)
            g_tokb[((size_t)(e * LP + l)) * C + tid + 256 * i] = z;
        return;
    }
    __shared__ float sa[16];
    if (tid < 16) sa[tid] = A[(e * L + l) * 16 + tid];
    __syncthreads();
    const float* Bp = Bm + (size_t)e * 16 * C;
    #pragma unroll
    for (int i = 0; i < 4; i++) {
        int c = tid + 256 * i;
        float acc = 0.f;
        #pragma unroll
        for (int r = 0; r < 16; r++) acc += sa[r] * Bp[r * C + c];
        g_tokens[((size_t)(e * L + l)) * C + c] = acc;
        g_tokb[((size_t)(e * LP + l)) * C + c] = __float2bfloat16(acc);
    }
}

// ---------------------------------------------------------------------------
// Kernel 3: val = tokens @ wt_w^T + wt_b -> bf16 TRANSPOSED [e][n][l]
// ---------------------------------------------------------------------------
__global__ __launch_bounds__(256) void val_gemm_kernel(
    const float* __restrict__ W, const float* __restrict__ bias)
{
    __shared__ float As[16][68];
    __shared__ float Bs[16][68];
    int e = blockIdx.z;
    const float* Amat = g_tokens + (size_t)e * L * C;
    int tid = threadIdx.x;
    int bm0 = blockIdx.y * 64;
    int bn0 = blockIdx.x * 64;
    int ty = tid >> 4, tx = tid & 15;
    int lr = tid >> 2, lk = (tid & 3) << 2;

    float acc[4][4];
    #pragma unroll
    for (int i = 0; i < 4; i++)
        #pragma unroll
        for (int j = 0; j < 4; j++) acc[i][j] = 0.f;

    for (int k0 = 0; k0 < C; k0 += 16) {
        int gm = bm0 + lr;
        float4 va = make_float4(0.f, 0.f, 0.f, 0.f);
        if (gm < L) va = *(const float4*)(Amat + (size_t)gm * C + k0 + lk);
        As[lk + 0][lr] = va.x; As[lk + 1][lr] = va.y;
        As[lk + 2][lr] = va.z; As[lk + 3][lr] = va.w;
        float4 vb = *(const float4*)(W + (size_t)(bn0 + lr) * C + k0 + lk);
        Bs[lk + 0][lr] = vb.x; Bs[lk + 1][lr] = vb.y;
        Bs[lk + 2][lr] = vb.z; Bs[lk + 3][lr] = vb.w;
        __syncthreads();
        #pragma unroll
        for (int kk = 0; kk < 16; kk++) {
            float4 a = *(float4*)&As[kk][ty * 4];
            float4 b = *(float4*)&Bs[kk][tx * 4];
            float af[4] = {a.x, a.y, a.z, a.w};
            float bf[4] = {b.x, b.y, b.z, b.w};
            #pragma unroll
            for (int i = 0; i < 4; i++)
                #pragma unroll
                for (int j = 0; j < 4; j++) acc[i][j] += af[i] * bf[j];
        }
        __syncthreads();
    }
    #pragma unroll
    for (int i = 0; i < 4; i++) {
        int l = bm0 + ty * 4 + i;
        #pragma unroll
        for (int j = 0; j < 4; j++) {
            int n = bn0 + tx * 4 + j;
            float v = (l < L) ? acc[i][j] + bias[n] : 0.f;
            g_valb[((size_t)e * C + n) * LP + l] = __float2bfloat16(v);
        }
    }
}

// ---------------------------------------------------------------------------
// Kernel 4: wd_w -> int8 (x SW_Q)
// ---------------------------------------------------------------------------
__global__ __launch_bounds__(256) void conv_wd_kernel(const float* __restrict__ W)
{
    int idx = blockIdx.x * 256 + threadIdx.x;   // one float4 each
    float4 v = *(const float4*)(W + (size_t)idx * 4);
    int a0 = clamp127(__float2int_rn(v.x * SW_Q));
    int a1 = clamp127(__float2int_rn(v.y * SW_Q));
    int a2 = clamp127(__float2int_rn(v.z * SW_Q));
    int a3 = clamp127(__float2int_rn(v.w * SW_Q));
    uint32_t packed = (uint32_t)(a0 & 0xff) | ((uint32_t)(a1 & 0xff) << 8) |
                      ((uint32_t)(a2 & 0xff) << 16) | ((uint32_t)(a3 & 0xff) << 24);
    *(uint32_t*)(g_wd8 + (size_t)idx * 4) = packed;
}

// ---------------------------------------------------------------------------
// Kernel 5: FUSED attn + combine (round-4 proven; epilogue now emits s8 u)
// ---------------------------------------------------------------------------
#define FUS_SMEM 95360
#define AS_A(s,r,c) (*(__nv_bfloat16*)(dyn + (((s)*32*40 + (r)*40 + (c)) << 1)))
#define BS_A(s,r,c) (*(__nv_bfloat16*)(dyn + 7680 + (((s)*128*40 + (r)*40 + (c)) << 1)))
#define VS_B(s,r,c) (*(__nv_bfloat16*)(dyn + (((s)*128*136 + (r)*136 + (c)) << 1)))
#define S_AT(r,c)   (*(float*)(dyn + 69632 + (((r)*132 + (c)) << 2)))
#define P_AT(r,c)   (*(__nv_bfloat16*)(dyn + 86528 + (((r)*136 + (c)) << 1)))
#define SIDX(i)     (*(int*)(dyn + 95232 + ((i) << 2)))

__global__ __launch_bounds__(256) void fused_attn_combine_kernel()
{
    extern __shared__ char dyn[];
    int e = blockIdx.x >> 8;
    int tile = blockIdx.x & 255;
    int cnt = g_cnt[e];
    if (tile * 32 >= cnt) return;

    int tid = threadIdx.x;
    if (tid < 32) {
        int slot = tile * 32 + tid;
        SIDX(tid) = (slot < cnt) ? g_idx[e * NTOK + slot] : -1;
    }
    __syncthreads();

    int lane = tid & 31, wid = tid >> 5;
    const __nv_bfloat16* tok = g_tokb + (size_t)e * LP * C;
    const __nv_bfloat16* val = g_valb + (size_t)e * C * LP;

    int wmA = (wid & 1) * 16;
    int wnA = (wid >> 1) * 32;

    float accA[4][4];
    #pragma unroll
    for (int ni = 0; ni < 4; ni++)
        #pragma unroll
        for (int q = 0; q < 4; q++) accA[ni][q] = 0.f;

    int ar = tid >> 2;
    int ac = (tid & 3) * 8;
    auto issueA = [&](int it, int s) {
        int k0 = it * 32;
        if (tid < 128) {
            int gi = SIDX(ar);
            const void* src = (gi >= 0) ? (const void*)(g_xb + (size_t)gi * C + k0 + ac)
                                        : (const void*)g_xb;
            cp16z(&AS_A(s, ar, ac), src, gi >= 0);
        }
        #pragma unroll
        for (int i = 0; i < 2; i++) {
            int idx = tid + i * 256;
            int r = idx >> 2, c8 = (idx & 3) * 8;
            cp16(&BS_A(s, r, c8), tok + (size_t)r * C + k0 + c8);
        }
        CP_COMMIT();
    };

    issueA(0, 0); issueA(1, 1);
    for (int it = 0; it < 32; it++) {
        int s = it % 3;
        if (it < 31) CP_WAIT1(); else CP_WAIT0();
        __syncthreads();
        if (it + 2 < 32) issueA(it + 2, (it + 2) % 3);
        #pragma unroll
        for (int ks = 0; ks < 32; ks += 16) {
            unsigned a[4], b[4][2];
            {
                unsigned addr = (unsigned)__cvta_generic_to_shared(
                    &AS_A(s, wmA + (lane & 15), ks + ((lane >> 4) << 3)));
                asm volatile("ldmatrix.sync.aligned.m8n8.x4.shared.b16 {%0,%1,%2,%3}, [%4];"
                    : "=r"(a[0]), "=r"(a[1]), "=r"(a[2]), "=r"(a[3]) : "r"(addr));
            }
            #pragma unroll
            for (int nj = 0; nj < 2; nj++) {
                unsigned addr = (unsigned)__cvta_generic_to_shared(
                    &BS_A(s, wnA + nj * 16 + ((lane >> 4) << 3) + (lane & 7),
                          ks + (((lane >> 3) & 1) << 3)));
                asm volatile("ldmatrix.sync.aligned.m8n8.x4.shared.b16 {%0,%1,%2,%3}, [%4];"
                    : "=r"(b[nj * 2][0]), "=r"(b[nj * 2][1]),
                      "=r"(b[nj * 2 + 1][0]), "=r"(b[nj * 2 + 1][1]) : "r"(addr));
            }
            #pragma unroll
            for (int ni = 0; ni < 4; ni++)
                asm volatile(
                    "mma.sync.aligned.m16n8k16.row.col.f32.bf16.bf16.f32 "
                    "{%0,%1,%2,%3}, {%4,%5,%6,%7}, {%8,%9}, {%0,%1,%2,%3};"
                    : "+f"(accA[ni][0]), "+f"(accA[ni][1]), "+f"(accA[ni][2]), "+f"(accA[ni][3])
                    : "r"(a[0]), "r"(a[1]), "r"(a[2]), "r"(a[3]),
                      "r"(b[ni][0]), "r"(b[ni][1]));
        }
    }

    int grp = lane >> 2, qid = lane & 3;
    #pragma unroll
    for (int ni = 0; ni < 4; ni++) {
        S_AT(wmA + grp,     wnA + ni * 8 + qid * 2)     = accA[ni][0] * 0.03125f;
        S_AT(wmA + grp,     wnA + ni * 8 + qid * 2 + 1) = accA[ni][1] * 0.03125f;
        S_AT(wmA + grp + 8, wnA + ni * 8 + qid * 2)     = accA[ni][2] * 0.03125f;
        S_AT(wmA + grp + 8, wnA + ni * 8 + qid * 2 + 1) = accA[ni][3] * 0.03125f;
    }
    __syncthreads();

    auto issueV = [&](int nc, int s) {
        #pragma unroll
        for (int i = 0; i < 8; i++) {
            int idx = tid + i * 256;
            int r = idx >> 4;
            int c8 = (idx & 15) * 8;
            cp16(&VS_B(s, r, c8), val + (size_t)(nc * 128 + r) * LP + c8);
        }
        CP_COMMIT();
    };
    issueV(0, 0);
    issueV(1, 1);

    for (int r = wid; r < 32; r += 8) {
        float mx = -INFINITY;
        for (int l = lane; l < L; l += 32) mx = fmaxf(mx, S_AT(r, l));
        #pragma unroll
        for (int o = 16; o; o >>= 1) mx = fmaxf(mx, __shfl_xor_sync(0xffffffffu, mx, o));
        float sum = 0.f, v[4];
        #pragma unroll
        for (int q = 0; q < 4; q++) {
            int l = lane + q * 32;
            v[q] = (l < L) ? expf(S_AT(r, l) - mx) : 0.f;
            sum += v[q];
        }
        #pragma unroll
        for (int o = 16; o; o >>= 1) sum += __shfl_xor_sync(0xffffffffu, sum, o);
        float inv = 1.f / sum;
        #pragma unroll
        for (int q = 0; q < 4; q++) {
            int l = lane + q * 32;
            float w = (l >= 1 && l < L) ? v[q] * inv : 0.f;
            P_AT(r, l) = __float2bfloat16(w);
        }
    }
    __syncthreads();

    for (int nc = 0; nc < 8; nc++) {
        int s = nc & 1;
        if (nc < 7) CP_WAIT1(); else CP_WAIT0();
        __syncthreads();

        float accB[2][2][4];
        #pragma unroll
        for (int mi = 0; mi < 2; mi++)
            #pragma unroll
            for (int ni = 0; ni < 2; ni++)
                #pragma unroll
                for (int q = 0; q < 4; q++) accB[mi][ni][q] = 0.f;

        #pragma unroll
        for (int ks = 0; ks < 128; ks += 16) {
            unsigned a[2][4], b[2][2];
            #pragma unroll
            for (int mi = 0; mi < 2; mi++) {
                unsigned addr = (unsigned)__cvta_generic_to_shared(
                    &P_AT(mi * 16 + (lane & 15), ks + ((lane >> 4) << 3)));
                asm volatile("ldmatrix.sync.aligned.m8n8.x4.shared.b16 {%0,%1,%2,%3}, [%4];"
                    : "=r"(a[mi][0]), "=r"(a[mi][1]), "=r"(a[mi][2]), "=r"(a[mi][3])
                    : "r"(addr));
            }
            {
                unsigned addr = (unsigned)__cvta_generic_to_shared(
                    &VS_B(s, wid * 16 + ((lane >> 4) << 3) + (lane & 7),
                          ks + (((lane >> 3) & 1) << 3)));
                asm volatile("ldmatrix.sync.aligned.m8n8.x4.shared.b16 {%0,%1,%2,%3}, [%4];"
                    : "=r"(b[0][0]), "=r"(b[0][1]), "=r"(b[1][0]), "=r"(b[1][1])
                    : "r"(addr));
            }
            #pragma unroll
            for (int mi = 0; mi < 2; mi++)
                #pragma unroll
                for (int ni = 0; ni < 2; ni++)
                    asm volatile(
                        "mma.sync.aligned.m16n8k16.row.col.f32.bf16.bf16.f32 "
                        "{%0,%1,%2,%3}, {%4,%5,%6,%7}, {%8,%9}, {%0,%1,%2,%3};"
                        : "+f"(accB[mi][ni][0]), "+f"(accB[mi][ni][1]),
                          "+f"(accB[mi][ni][2]), "+f"(accB[mi][ni][3])
                        : "r"(a[mi][0]), "r"(a[mi][1]), "r"(a[mi][2]), "r"(a[mi][3]),
                          "r"(b[ni][0]), "r"(b[ni][1]));
        }
        __syncthreads();
        if (nc + 2 < 8) issueV(nc + 2, s);

        #pragma unroll
        for (int mi = 0; mi < 2; mi++) {
            #pragma unroll
            for (int ni = 0; ni < 2; ni++) {
                #pragma unroll
                for (int half = 0; half < 2; half++) {
                    int m = mi * 16 + grp + half * 8;
                    int gi = SIDX(m);
                    if (gi < 0) continue;
                    int n = nc * 128 + wid * 16 + ni * 8 + qid * 2;
                    size_t xi = (size_t)gi * C + n;
                    __nv_bfloat162 xv = *(const __nv_bfloat162*)(g_xb + xi);
                    float u0 = __bfloat162float(xv.x) + accB[mi][ni][half * 2];
                    float u1 = __bfloat162float(xv.y) + accB[mi][ni][half * 2 + 1];
                    int q0 = clamp127(__float2int_rn(u0 * SU_Q));
                    int q1 = clamp127(__float2int_rn(u1 * SU_Q));
                    *(char2*)(g_u8 + xi) = make_char2((char)q0, (char)q1);
                }
            }
        }
    }
}

// ---------------------------------------------------------------------------
// Kernel 6: final GEMM in INT8 (mma m16n8k32.s8), s32 exact accumulation:
// out = feats + ((s32acc)/(SU*SW) + bias)*scale. 128x128x1024 tiles,
// 16 chunks of k=64 s8 (same [128][40]-b16 smem layout as the bf16 kernel),
// 4-stage/3-deep cp.async, 1 sync per k-iter. grid (8, 64).
// ---------------------------------------------------------------------------
#define FIN_SMEM 81920
#define AS_F(s,r,c) (*(__nv_bfloat16*)(dynf + (((s)*128*40 + (r)*40 + (c)) << 1)))
#define BS_F(s,r,c) (*(__nv_bfloat16*)(dynf + 40960 + (((s)*128*40 + (r)*40 + (c)) << 1)))

__global__ __launch_bounds__(256) void final_mma_kernel(
    const float* __restrict__ bias, const float* __restrict__ feats,
    const float* __restrict__ scale_p, float* __restrict__ out)
{
    extern __shared__ char dynf[];
    int tid = threadIdx.x;
    int wid = tid >> 5, lane = tid & 31;
    int wm = (wid & 3) * 32;
    int wn = (wid >> 2) * 64;
    int bm0 = blockIdx.y * 128;
    int bn0 = blockIdx.x * 128;

    int acc[2][8][4];
    #pragma unroll
    for (int mi = 0; mi < 2; mi++)
        #pragma unroll
        for (int ni = 0; ni < 8; ni++)
            #pragma unroll
            for (int q = 0; q < 4; q++) acc[mi][ni][q] = 0;

    // per chunk: 128 rows x 64 s8 per operand; 16B segments
    int lr = tid >> 1;                 // 0..127
    int lj = (tid & 1) * 2;            // segment pairs
    auto issue = [&](int chunk, int s) {
        int k0 = chunk * 64;
        #pragma unroll
        for (int i = 0; i < 2; i++) {
            int j = lj + i;            // 0..3 (16B segment within 64B row)
            cp16(&AS_F(s, lr, j * 8), g_u8  + (size_t)(bm0 + lr) * C + k0 + j * 16);
            cp16(&BS_F(s, lr, j * 8), g_wd8 + (size_t)(bn0 + lr) * C + k0 + j * 16);
        }
        CP_COMMIT();
    };

    issue(0, 0); issue(1, 1); issue(2, 2);
    for (int it = 0; it < 16; it++) {
        int s = it & 3;
        if (it < 14) CP_WAIT2();
        else if (it == 14) CP_WAIT1();
        else CP_WAIT0();
        __syncthreads();
        if (it + 3 < 16) issue(it + 3, (it + 3) & 3);
        #pragma unroll
        for (int ks = 0; ks < 32; ks += 16) {   // b16-unit cols; each = k32 s8 mma
            unsigned a[2][4], b[8][2];
            #pragma unroll
            for (int mi = 0; mi < 2; mi++) {
                unsigned addr = (unsigned)__cvta_generic_to_shared(
                    &AS_F(s, wm + mi * 16 + (lane & 15), ks + ((lane >> 4) << 3)));
                asm volatile("ldmatrix.sync.aligned.m8n8.x4.shared.b16 {%0,%1,%2,%3}, [%4];"
                    : "=r"(a[mi][0]), "=r"(a[mi][1]), "=r"(a[mi][2]), "=r"(a[mi][3])
                    : "r"(addr));
            }
            #pragma unroll
            for (int nj = 0; nj < 4; nj++) {
                unsigned addr = (unsigned)__cvta_generic_to_shared(
                    &BS_F(s, wn + nj * 16 + ((lane >> 4) << 3) + (lane & 7),
                          ks + (((lane >> 3) & 1) << 3)));
                asm volatile("ldmatrix.sync.aligned.m8n8.x4.shared.b16 {%0,%1,%2,%3}, [%4];"
                    : "=r"(b[nj * 2][0]), "=r"(b[nj * 2][1]),
                      "=r"(b[nj * 2 + 1][0]), "=r"(b[nj * 2 + 1][1]) : "r"(addr));
            }
            #pragma unroll
            for (int mi = 0; mi < 2; mi++)
                #pragma unroll
                for (int ni = 0; ni < 8; ni++)
                    asm volatile(
                        "mma.sync.aligned.m16n8k32.row.col.s32.s8.s8.s32 "
                        "{%0,%1,%2,%3}, {%4,%5,%6,%7}, {%8,%9}, {%0,%1,%2,%3};"
                        : "+r"(acc[mi][ni][0]), "+r"(acc[mi][ni][1]),
                          "+r"(acc[mi][ni][2]), "+r"(acc[mi][ni][3])
                        : "r"(a[mi][0]), "r"(a[mi][1]), "r"(a[mi][2]), "r"(a[mi][3]),
                          "r"(b[ni][0]), "r"(b[ni][1]));
        }
    }

    float sc = scale_p[0];
    int grp = lane >> 2, qid = lane & 3;
    #pragma unroll
    for (int mi = 0; mi < 2; mi++) {
        #pragma unroll
        for (int ni = 0; ni < 8; ni++) {
            int m = bm0 + wm + mi * 16 + grp;
            int n = bn0 + wn + ni * 8 + qid * 2;
            size_t i0 = (size_t)m * C + n;
            size_t i1 = (size_t)(m + 8) * C + n;
            float b0 = bias[n], b1 = bias[n + 1];
            out[i0]     = feats[i0]     + ((float)acc[mi][ni][0] * INV_Q + b0) * sc;
            out[i0 + 1] = feats[i0 + 1] + ((float)acc[mi][ni][1] * INV_Q + b1) * sc;
            out[i1]     = feats[i1]     + ((float)acc[mi][ni][2] * INV_Q + b0) * sc;
            out[i1 + 1] = feats[i1 + 1] + ((float)acc[mi][ni][3] * INV_Q + b1) * sc;
        }
    }
}

// ---------------------------------------------------------------------------
// Launch. Inputs: 0 feats, 1 A, 2 B, 3 w_gate, 4 wt_w, 5 wt_b, 6 wd_w,
//                 7 wd_b, 8 scale
// ---------------------------------------------------------------------------
extern "C" void kernel_launch(void* const* d_in, const int* in_sizes, int n_in,
                              void* d_out, int out_size)
{
    const float* feats  = (const float*)d_in[0];
    const float* A      = (const float*)d_in[1];
    const float* Bm     = (const float*)d_in[2];
    const float* w_gate = (const float*)d_in[3];
    const float* wt_w   = (const float*)d_in[4];
    const float* wt_b   = (const float*)d_in[5];
    const float* wd_w   = (const float*)d_in[6];
    const float* wd_b   = (const float*)d_in[7];
    const float* scale  = (const float*)d_in[8];
    float* out = (float*)d_out;

    cudaFuncSetAttribute(fused_attn_combine_kernel,
                         cudaFuncAttributeMaxDynamicSharedMemorySize, FUS_SMEM);
    cudaFuncSetAttribute(final_mma_kernel,
                         cudaFuncAttributeMaxDynamicSharedMemorySize, FIN_SMEM);

    int* cnt_p; cudaGetSymbolAddress((void**)&cnt_p, g_cnt);
    cudaMemsetAsync(cnt_p, 0, E * sizeof(int));

    conv_gate_kernel<<<NTOK / 8, 256>>>(feats, w_gate);
    tokens_kernel<<<E * 128, 256>>>(A, Bm);
    val_gemm_kernel<<<dim3(16, 2, E), 256>>>(wt_w, wt_b);
    conv_wd_kernel<<<1024, 256>>>(wd_w);
    fused_attn_combine_kernel<<<E * 256, 256, FUS_SMEM>>>();
    final_mma_kernel<<<dim3(8, 64), 256, FIN_SMEM>>>(wd_b, feats, scale, out);
}

// round 9
// speedup vs baseline: 4.5995x; 1.0527x over previous
#include <cuda_runtime.h>
#include <cuda_bf16.h>
#include <math.h>
#include <cstdint>

#define NTOK 8192
#define C    1024
#define E    6
#define L    100
#define LP   128      // L padded

// int8 quantization scales for the final GEMM
#define SU_Q 24.0f
#define SW_Q 800.0f
#define INV_Q (1.0f / (24.0f * 800.0f))

// Scratch
__device__ float g_tokens[E * L * C];                 // fp32 tokens [e][l][c]
__device__ __nv_bfloat16 g_tokb[E * LP * C];          // bf16 tokens, L-padded
__device__ __nv_bfloat16 g_valb[E * C * LP];          // bf16 val, TRANSPOSED [e][c][l]
__device__ __nv_bfloat16 g_xb[NTOK * C];              // bf16 feats
__device__ int8_t g_u8[NTOK * C];                     // s8 u = x + delta_f (x SU_Q)
__device__ int8_t g_wd8[C * C];                       // s8 wd_w (x SW_Q)
__device__ int g_idx[E * NTOK];
__device__ int g_cnt[E];

// ---------------------------------------------------------------------------
// cp.async helpers
// ---------------------------------------------------------------------------
__device__ __forceinline__ void cp16(void* smem, const void* gmem) {
    unsigned s = (unsigned)__cvta_generic_to_shared(smem);
    asm volatile("cp.async.cg.shared.global [%0], [%1], 16;\n" :: "r"(s), "l"(gmem));
}
__device__ __forceinline__ void cp16z(void* smem, const void* gmem, bool valid) {
    unsigned s = (unsigned)__cvta_generic_to_shared(smem);
    int sz = valid ? 16 : 0;
    asm volatile("cp.async.cg.shared.global [%0], [%1], 16, %2;\n" :: "r"(s), "l"(gmem), "r"(sz));
}
#define CP_COMMIT() asm volatile("cp.async.commit_group;\n")
#define CP_WAIT2()  asm volatile("cp.async.wait_group 2;\n")
#define CP_WAIT1()  asm volatile("cp.async.wait_group 1;\n")
#define CP_WAIT0()  asm volatile("cp.async.wait_group 0;\n")

__device__ __forceinline__ int clamp127(int v) {
    return v > 127 ? 127 : (v < -127 ? -127 : v);
}

// ---------------------------------------------------------------------------
// Kernel 1 (merged prep): block-range dispatch.
//  blocks [0,1024):    conv_gate — feats->bf16 + gating argmax + compaction
//  blocks [1024,1792): tokens    — A@B -> g_tokens fp32 + g_tokb bf16 padded
//  blocks [1792,2816): conv_wd   — wd_w -> s8
// ---------------------------------------------------------------------------
__global__ __launch_bounds__(256) void prep_kernel(
    const float* __restrict__ feats, const float* __restrict__ w_gate,
    const float* __restrict__ A, const float* __restrict__ Bm,
    const float* __restrict__ W)
{
    __shared__ float sw[E * C];
    int blk = blockIdx.x;
    int tid = threadIdx.x;

    if (blk < 1024) {
        // ---- conv_gate ----
        for (int i = tid; i < E * C; i += 256) {
            int e = i >> 10, c = i & 1023;
            sw[i] = w_gate[c * E + e];
        }
        __syncthreads();
        int lane = tid & 31, wid = tid >> 5;
        int t = blk * 8 + wid;
        const float* x = feats + (size_t)t * C;
        __nv_bfloat16* xb = g_xb + (size_t)t * C;

        float acc[E];
        #pragma unroll
        for (int e = 0; e < E; e++) acc[e] = 0.f;

        #pragma unroll
        for (int i = 0; i < 8; i++) {
            int c0 = 4 * (lane + 32 * i);
            float4 v = *(const float4*)(x + c0);
            __nv_bfloat162 h0 = __float22bfloat162_rn(make_float2(v.x, v.y));
            __nv_bfloat162 h1 = __float22bfloat162_rn(make_float2(v.z, v.w));
            uint2 p; p.x = *(unsigned*)&h0; p.y = *(unsigned*)&h1;
            *(uint2*)(xb + c0) = p;
            #pragma unroll
            for (int e = 0; e < E; e++) {
                float4 w = *(const float4*)&sw[e * C + c0];
                acc[e] += v.x * w.x + v.y * w.y + v.z * w.z + v.w * w.w;
            }
        }
        #pragma unroll
        for (int e = 0; e < E; e++)
            #pragma unroll
            for (int o = 16; o; o >>= 1) acc[e] += __shfl_xor_sync(0xffffffffu, acc[e], o);
        if (lane == 0) {
            int best = 0; float bv = acc[0];
            #pragma unroll
            for (int e = 1; e < E; e++)
                if (acc[e] > bv) { bv = acc[e]; best = e; }
            int pos = atomicAdd(&g_cnt[best], 1);
            g_idx[best * NTOK + pos] = t;
        }
    } else if (blk < 1792) {
        // ---- tokens ----
        int b = blk - 1024;
        int e = b >> 7, l = b & 127;
        if (l >= L) {
            __nv_bfloat16 z = __float2bfloat16(0.f);
            #pragma unroll
            for (int i = 0; i < 4; i++)
                g_tokb[((size_t)(e * LP + l)) * C + tid + 256 * i] = z;
            return;
        }
        if (tid < 16) sw[tid] = A[(e * L + l) * 16 + tid];
        __syncthreads();
        const float* Bp = Bm + (size_t)e * 16 * C;
        #pragma unroll
        for (int i = 0; i < 4; i++) {
            int c = tid + 256 * i;
            float acc = 0.f;
            #pragma unroll
            for (int r = 0; r < 16; r++) acc += sw[r] * Bp[r * C + c];
            g_tokens[((size_t)(e * L + l)) * C + c] = acc;
            g_tokb[((size_t)(e * LP + l)) * C + c] = __float2bfloat16(acc);
        }
    } else {
        // ---- conv_wd ----
        int idx = (blk - 1792) * 256 + tid;
        float4 v = *(const float4*)(W + (size_t)idx * 4);
        int a0 = clamp127(__float2int_rn(v.x * SW_Q));
        int a1 = clamp127(__float2int_rn(v.y * SW_Q));
        int a2 = clamp127(__float2int_rn(v.z * SW_Q));
        int a3 = clamp127(__float2int_rn(v.w * SW_Q));
        uint32_t packed = (uint32_t)(a0 & 0xff) | ((uint32_t)(a1 & 0xff) << 8) |
                          ((uint32_t)(a2 & 0xff) << 16) | ((uint32_t)(a3 & 0xff) << 24);
        *(uint32_t*)(g_wd8 + (size_t)idx * 4) = packed;
    }
}

// ---------------------------------------------------------------------------
// Kernel 2: val = tokens @ wt_w^T + wt_b -> bf16 TRANSPOSED [e][n][l]
// ---------------------------------------------------------------------------
__global__ __launch_bounds__(256) void val_gemm_kernel(
    const float* __restrict__ W, const float* __restrict__ bias)
{
    __shared__ float As[16][68];
    __shared__ float Bs[16][68];
    int e = blockIdx.z;
    const float* Amat = g_tokens + (size_t)e * L * C;
    int tid = threadIdx.x;
    int bm0 = blockIdx.y * 64;
    int bn0 = blockIdx.x * 64;
    int ty = tid >> 4, tx = tid & 15;
    int lr = tid >> 2, lk = (tid & 3) << 2;

    float acc[4][4];
    #pragma unroll
    for (int i = 0; i < 4; i++)
        #pragma unroll
        for (int j = 0; j < 4; j++) acc[i][j] = 0.f;

    for (int k0 = 0; k0 < C; k0 += 16) {
        int gm = bm0 + lr;
        float4 va = make_float4(0.f, 0.f, 0.f, 0.f);
        if (gm < L) va = *(const float4*)(Amat + (size_t)gm * C + k0 + lk);
        As[lk + 0][lr] = va.x; As[lk + 1][lr] = va.y;
        As[lk + 2][lr] = va.z; As[lk + 3][lr] = va.w;
        float4 vb = *(const float4*)(W + (size_t)(bn0 + lr) * C + k0 + lk);
        Bs[lk + 0][lr] = vb.x; Bs[lk + 1][lr] = vb.y;
        Bs[lk + 2][lr] = vb.z; Bs[lk + 3][lr] = vb.w;
        __syncthreads();
        #pragma unroll
        for (int kk = 0; kk < 16; kk++) {
            float4 a = *(float4*)&As[kk][ty * 4];
            float4 b = *(float4*)&Bs[kk][tx * 4];
            float af[4] = {a.x, a.y, a.z, a.w};
            float bf[4] = {b.x, b.y, b.z, b.w};
            #pragma unroll
            for (int i = 0; i < 4; i++)
                #pragma unroll
                for (int j = 0; j < 4; j++) acc[i][j] += af[i] * bf[j];
        }
        __syncthreads();
    }
    #pragma unroll
    for (int i = 0; i < 4; i++) {
        int l = bm0 + ty * 4 + i;
        #pragma unroll
        for (int j = 0; j < 4; j++) {
            int n = bn0 + tx * 4 + j;
            float v = (l < L) ? acc[i][j] + bias[n] : 0.f;
            g_valb[((size_t)e * C + n) * LP + l] = __float2bfloat16(v);
        }
    }
}

// ---------------------------------------------------------------------------
// Kernel 3: FUSED attn + combine. Phase A k-chunk 64 (16 iterations).
// Dynamic smem layout (bytes):
//  [0, 69632):  union { phase A: As[3][32][72] (13824) + Bs[3][128][72] (55296);
//                       phase B: Vs[2][128][136] (69632) }
//  [69632, 86528): S fp32 [32][132]
//  [86528, 95232): P bf16 [32][136]
//  [95232, 95360): sidx[32]
// ---------------------------------------------------------------------------
#define FUS_SMEM 95360
#define AS_A(s,r,c) (*(__nv_bfloat16*)(dyn + (((s)*32*72 + (r)*72 + (c)) << 1)))
#define BS_A(s,r,c) (*(__nv_bfloat16*)(dyn + 13824 + (((s)*128*72 + (r)*72 + (c)) << 1)))
#define VS_B(s,r,c) (*(__nv_bfloat16*)(dyn + (((s)*128*136 + (r)*136 + (c)) << 1)))
#define S_AT(r,c)   (*(float*)(dyn + 69632 + (((r)*132 + (c)) << 2)))
#define P_AT(r,c)   (*(__nv_bfloat16*)(dyn + 86528 + (((r)*136 + (c)) << 1)))
#define SIDX(i)     (*(int*)(dyn + 95232 + ((i) << 2)))

__global__ __launch_bounds__(256) void fused_attn_combine_kernel()
{
    extern __shared__ char dyn[];
    int e = blockIdx.x >> 8;
    int tile = blockIdx.x & 255;
    int cnt = g_cnt[e];
    if (tile * 32 >= cnt) return;

    int tid = threadIdx.x;
    if (tid < 32) {
        int slot = tile * 32 + tid;
        SIDX(tid) = (slot < cnt) ? g_idx[e * NTOK + slot] : -1;
    }
    __syncthreads();

    int lane = tid & 31, wid = tid >> 5;
    const __nv_bfloat16* tok = g_tokb + (size_t)e * LP * C;
    const __nv_bfloat16* val = g_valb + (size_t)e * C * LP;

    int wmA = (wid & 1) * 16;
    int wnA = (wid >> 1) * 32;

    float accA[4][4];
    #pragma unroll
    for (int ni = 0; ni < 4; ni++)
        #pragma unroll
        for (int q = 0; q < 4; q++) accA[ni][q] = 0.f;

    // phase A loader: A tile 32x64 (256 segs), B tile 128x64 (1024 segs)
    int ar = tid >> 3;              // 0..31
    int ac = (tid & 7) * 8;         // 0..56
    auto issueA = [&](int it, int s) {
        int k0 = it * 64;
        {
            int gi = SIDX(ar);
            const void* src = (gi >= 0) ? (const void*)(g_xb + (size_t)gi * C + k0 + ac)
                                        : (const void*)g_xb;
            cp16z(&AS_A(s, ar, ac), src, gi >= 0);
        }
        #pragma unroll
        for (int i = 0; i < 4; i++) {
            int idx = tid + i * 256;
            int r = idx >> 3, c8 = (idx & 7) * 8;
            cp16(&BS_A(s, r, c8), tok + (size_t)r * C + k0 + c8);
        }
        CP_COMMIT();
    };

    issueA(0, 0); issueA(1, 1);
    for (int it = 0; it < 16; it++) {
        int s = it % 3;
        if (it < 15) CP_WAIT1(); else CP_WAIT0();
        __syncthreads();
        if (it + 2 < 16) issueA(it + 2, (it + 2) % 3);
        #pragma unroll
        for (int ks = 0; ks < 64; ks += 16) {
            unsigned a[4], b[4][2];
            {
                unsigned addr = (unsigned)__cvta_generic_to_shared(
                    &AS_A(s, wmA + (lane & 15), ks + ((lane >> 4) << 3)));
                asm volatile("ldmatrix.sync.aligned.m8n8.x4.shared.b16 {%0,%1,%2,%3}, [%4];"
                    : "=r"(a[0]), "=r"(a[1]), "=r"(a[2]), "=r"(a[3]) : "r"(addr));
            }
            #pragma unroll
            for (int nj = 0; nj < 2; nj++) {
                unsigned addr = (unsigned)__cvta_generic_to_shared(
                    &BS_A(s, wnA + nj * 16 + ((lane >> 4) << 3) + (lane & 7),
                          ks + (((lane >> 3) & 1) << 3)));
                asm volatile("ldmatrix.sync.aligned.m8n8.x4.shared.b16 {%0,%1,%2,%3}, [%4];"
                    : "=r"(b[nj * 2][0]), "=r"(b[nj * 2][1]),
                      "=r"(b[nj * 2 + 1][0]), "=r"(b[nj * 2 + 1][1]) : "r"(addr));
            }
            #pragma unroll
            for (int ni = 0; ni < 4; ni++)
                asm volatile(
                    "mma.sync.aligned.m16n8k16.row.col.f32.bf16.bf16.f32 "
                    "{%0,%1,%2,%3}, {%4,%5,%6,%7}, {%8,%9}, {%0,%1,%2,%3};"
                    : "+f"(accA[ni][0]), "+f"(accA[ni][1]), "+f"(accA[ni][2]), "+f"(accA[ni][3])
                    : "r"(a[0]), "r"(a[1]), "r"(a[2]), "r"(a[3]),
                      "r"(b[ni][0]), "r"(b[ni][1]));
        }
    }

    int grp = lane >> 2, qid = lane & 3;
    #pragma unroll
    for (int ni = 0; ni < 4; ni++) {
        S_AT(wmA + grp,     wnA + ni * 8 + qid * 2)     = accA[ni][0] * 0.03125f;
        S_AT(wmA + grp,     wnA + ni * 8 + qid * 2 + 1) = accA[ni][1] * 0.03125f;
        S_AT(wmA + grp + 8, wnA + ni * 8 + qid * 2)     = accA[ni][2] * 0.03125f;
        S_AT(wmA + grp + 8, wnA + ni * 8 + qid * 2 + 1) = accA[ni][3] * 0.03125f;
    }
    __syncthreads();   // phase A smem reads complete

    auto issueV = [&](int nc, int s) {
        #pragma unroll
        for (int i = 0; i < 8; i++) {
            int idx = tid + i * 256;
            int r = idx >> 4;
            int c8 = (idx & 15) * 8;
            cp16(&VS_B(s, r, c8), val + (size_t)(nc * 128 + r) * LP + c8);
        }
        CP_COMMIT();
    };
    issueV(0, 0);
    issueV(1, 1);

    for (int r = wid; r < 32; r += 8) {
        float mx = -INFINITY;
        for (int l = lane; l < L; l += 32) mx = fmaxf(mx, S_AT(r, l));
        #pragma unroll
        for (int o = 16; o; o >>= 1) mx = fmaxf(mx, __shfl_xor_sync(0xffffffffu, mx, o));
        float sum = 0.f, v[4];
        #pragma unroll
        for (int q = 0; q < 4; q++) {
            int l = lane + q * 32;
            v[q] = (l < L) ? expf(S_AT(r, l) - mx) : 0.f;
            sum += v[q];
        }
        #pragma unroll
        for (int o = 16; o; o >>= 1) sum += __shfl_xor_sync(0xffffffffu, sum, o);
        float inv = 1.f / sum;
        #pragma unroll
        for (int q = 0; q < 4; q++) {
            int l = lane + q * 32;
            float w = (l >= 1 && l < L) ? v[q] * inv : 0.f;
            P_AT(r, l) = __float2bfloat16(w);
        }
    }
    __syncthreads();

    for (int nc = 0; nc < 8; nc++) {
        int s = nc & 1;
        if (nc < 7) CP_WAIT1(); else CP_WAIT0();
        __syncthreads();

        float accB[2][2][4];
        #pragma unroll
        for (int mi = 0; mi < 2; mi++)
            #pragma unroll
            for (int ni = 0; ni < 2; ni++)
                #pragma unroll
                for (int q = 0; q < 4; q++) accB[mi][ni][q] = 0.f;

        #pragma unroll
        for (int ks = 0; ks < 128; ks += 16) {
            unsigned a[2][4], b[2][2];
            #pragma unroll
            for (int mi = 0; mi < 2; mi++) {
                unsigned addr = (unsigned)__cvta_generic_to_shared(
                    &P_AT(mi * 16 + (lane & 15), ks + ((lane >> 4) << 3)));
                asm volatile("ldmatrix.sync.aligned.m8n8.x4.shared.b16 {%0,%1,%2,%3}, [%4];"
                    : "=r"(a[mi][0]), "=r"(a[mi][1]), "=r"(a[mi][2]), "=r"(a[mi][3])
                    : "r"(addr));
            }
            {
                unsigned addr = (unsigned)__cvta_generic_to_shared(
                    &VS_B(s, wid * 16 + ((lane >> 4) << 3) + (lane & 7),
                          ks + (((lane >> 3) & 1) << 3)));
                asm volatile("ldmatrix.sync.aligned.m8n8.x4.shared.b16 {%0,%1,%2,%3}, [%4];"
                    : "=r"(b[0][0]), "=r"(b[0][1]), "=r"(b[1][0]), "=r"(b[1][1])
                    : "r"(addr));
            }
            #pragma unroll
            for (int mi = 0; mi < 2; mi++)
                #pragma unroll
                for (int ni = 0; ni < 2; ni++)
                    asm volatile(
                        "mma.sync.aligned.m16n8k16.row.col.f32.bf16.bf16.f32 "
                        "{%0,%1,%2,%3}, {%4,%5,%6,%7}, {%8,%9}, {%0,%1,%2,%3};"
                        : "+f"(accB[mi][ni][0]), "+f"(accB[mi][ni][1]),
                          "+f"(accB[mi][ni][2]), "+f"(accB[mi][ni][3])
                        : "r"(a[mi][0]), "r"(a[mi][1]), "r"(a[mi][2]), "r"(a[mi][3]),
                          "r"(b[ni][0]), "r"(b[ni][1]));
        }
        __syncthreads();
        if (nc + 2 < 8) issueV(nc + 2, s);

        #pragma unroll
        for (int mi = 0; mi < 2; mi++) {
            #pragma unroll
            for (int ni = 0; ni < 2; ni++) {
                #pragma unroll
                for (int half = 0; half < 2; half++) {
                    int m = mi * 16 + grp + half * 8;
                    int gi = SIDX(m);
                    if (gi < 0) continue;
                    int n = nc * 128 + wid * 16 + ni * 8 + qid * 2;
                    size_t xi = (size_t)gi * C + n;
                    __nv_bfloat162 xv = *(const __nv_bfloat162*)(g_xb + xi);
                    float u0 = __bfloat162float(xv.x) + accB[mi][ni][half * 2];
                    float u1 = __bfloat162float(xv.y) + accB[mi][ni][half * 2 + 1];
                    int q0 = clamp127(__float2int_rn(u0 * SU_Q));
                    int q1 = clamp127(__float2int_rn(u1 * SU_Q));
                    *(char2*)(g_u8 + xi) = make_char2((char)q0, (char)q1);
                }
            }
        }
    }
}

// ---------------------------------------------------------------------------
// Kernel 4: final GEMM in INT8 (mma m16n8k32.s8), k-chunk 128 (8 iterations),
// 4-stage/3-deep cp.async, 1 sync per k-iter. grid (8, 64).
// Smem: As[4][128][72]b16 (73728B) + Bs same = 147456B.
// ---------------------------------------------------------------------------
#define FIN_SMEM 147456
#define AS_F(s,r,c) (*(__nv_bfloat16*)(dynf + (((s)*128*72 + (r)*72 + (c)) << 1)))
#define BS_F(s,r,c) (*(__nv_bfloat16*)(dynf + 73728 + (((s)*128*72 + (r)*72 + (c)) << 1)))

__global__ __launch_bounds__(256) void final_mma_kernel(
    const float* __restrict__ bias, const float* __restrict__ feats,
    const float* __restrict__ scale_p, float* __restrict__ out)
{
    extern __shared__ char dynf[];
    int tid = threadIdx.x;
    int wid = tid >> 5, lane = tid & 31;
    int wm = (wid & 3) * 32;
    int wn = (wid >> 2) * 64;
    int bm0 = blockIdx.y * 128;
    int bn0 = blockIdx.x * 128;

    int acc[2][8][4];
    #pragma unroll
    for (int mi = 0; mi < 2; mi++)
        #pragma unroll
        for (int ni = 0; ni < 8; ni++)
            #pragma unroll
            for (int q = 0; q < 4; q++) acc[mi][ni][q] = 0;

    // per chunk: 128 rows x 128 s8 per operand = 1024 x 16B segments each
    auto issue = [&](int chunk, int s) {
        int k0 = chunk * 128;
        #pragma unroll
        for (int i = 0; i < 4; i++) {
            int idx = tid + i * 256;
            int r = idx >> 3;          // 0..127
            int j = idx & 7;           // 16B segment
            cp16(&AS_F(s, r, j * 8), g_u8  + (size_t)(bm0 + r) * C + k0 + j * 16);
            cp16(&BS_F(s, r, j * 8), g_wd8 + (size_t)(bn0 + r) * C + k0 + j * 16);
        }
        CP_COMMIT();
    };

    issue(0, 0); issue(1, 1); issue(2, 2);
    for (int it = 0; it < 8; it++) {
        int s = it & 3;
        if (it < 6) CP_WAIT2();
        else if (it == 6) CP_WAIT1();
        else CP_WAIT0();
        __syncthreads();
        if (it + 3 < 8) issue(it + 3, (it + 3) & 3);
        #pragma unroll
        for (int ks = 0; ks < 64; ks += 16) {   // b16-unit cols; each = k32 s8 mma
            unsigned a[2][4], b[8][2];
            #pragma unroll
            for (int mi = 0; mi < 2; mi++) {
                unsigned addr = (unsigned)__cvta_generic_to_shared(
                    &AS_F(s, wm + mi * 16 + (lane & 15), ks + ((lane >> 4) << 3)));
                asm volatile("ldmatrix.sync.aligned.m8n8.x4.shared.b16 {%0,%1,%2,%3}, [%4];"
                    : "=r"(a[mi][0]), "=r"(a[mi][1]), "=r"(a[mi][2]), "=r"(a[mi][3])
                    : "r"(addr));
            }
            #pragma unroll
            for (int nj = 0; nj < 4; nj++) {
                unsigned addr = (unsigned)__cvta_generic_to_shared(
                    &BS_F(s, wn + nj * 16 + ((lane >> 4) << 3) + (lane & 7),
                          ks + (((lane >> 3) & 1) << 3)));
                asm volatile("ldmatrix.sync.aligned.m8n8.x4.shared.b16 {%0,%1,%2,%3}, [%4];"
                    : "=r"(b[nj * 2][0]), "=r"(b[nj * 2][1]),
                      "=r"(b[nj * 2 + 1][0]), "=r"(b[nj * 2 + 1][1]) : "r"(addr));
            }
            #pragma unroll
            for (int mi = 0; mi < 2; mi++)
                #pragma unroll
                for (int ni = 0; ni < 8; ni++)
                    asm volatile(
                        "mma.sync.aligned.m16n8k32.row.col.s32.s8.s8.s32 "
                        "{%0,%1,%2,%3}, {%4,%5,%6,%7}, {%8,%9}, {%0,%1,%2,%3};"
                        : "+r"(acc[mi][ni][0]), "+r"(acc[mi][ni][1]),
                          "+r"(acc[mi][ni][2]), "+r"(acc[mi][ni][3])
                        : "r"(a[mi][0]), "r"(a[mi][1]), "r"(a[mi][2]), "r"(a[mi][3]),
                          "r"(b[ni][0]), "r"(b[ni][1]));
        }
    }

    float sc = scale_p[0];
    int grp = lane >> 2, qid = lane & 3;
    #pragma unroll
    for (int mi = 0; mi < 2; mi++) {
        #pragma unroll
        for (int ni = 0; ni < 8; ni++) {
            int m = bm0 + wm + mi * 16 + grp;
            int n = bn0 + wn + ni * 8 + qid * 2;
            size_t i0 = (size_t)m * C + n;
            size_t i1 = (size_t)(m + 8) * C + n;
            float b0 = bias[n], b1 = bias[n + 1];
            out[i0]     = feats[i0]     + ((float)acc[mi][ni][0] * INV_Q + b0) * sc;
            out[i0 + 1] = feats[i0 + 1] + ((float)acc[mi][ni][1] * INV_Q + b1) * sc;
            out[i1]     = feats[i1]     + ((float)acc[mi][ni][2] * INV_Q + b0) * sc;
            out[i1 + 1] = feats[i1 + 1] + ((float)acc[mi][ni][3] * INV_Q + b1) * sc;
        }
    }
}

// ---------------------------------------------------------------------------
// Launch. Inputs: 0 feats, 1 A, 2 B, 3 w_gate, 4 wt_w, 5 wt_b, 6 wd_w,
//                 7 wd_b, 8 scale
// ---------------------------------------------------------------------------
extern "C" void kernel_launch(void* const* d_in, const int* in_sizes, int n_in,
                              void* d_out, int out_size)
{
    const float* feats  = (const float*)d_in[0];
    const float* A      = (const float*)d_in[1];
    const float* Bm     = (const float*)d_in[2];
    const float* w_gate = (const float*)d_in[3];
    const float* wt_w   = (const float*)d_in[4];
    const float* wt_b   = (const float*)d_in[5];
    const float* wd_w   = (const float*)d_in[6];
    const float* wd_b   = (const float*)d_in[7];
    const float* scale  = (const float*)d_in[8];
    float* out = (float*)d_out;

    cudaFuncSetAttribute(fused_attn_combine_kernel,
                         cudaFuncAttributeMaxDynamicSharedMemorySize, FUS_SMEM);
    cudaFuncSetAttribute(final_mma_kernel,
                         cudaFuncAttributeMaxDynamicSharedMemorySize, FIN_SMEM);

    int* cnt_p; cudaGetSymbolAddress((void**)&cnt_p, g_cnt);
    cudaMemsetAsync(cnt_p, 0, E * sizeof(int));

    prep_kernel<<<2816, 256>>>(feats, w_gate, A, Bm, wd_w);
    val_gemm_kernel<<<dim3(16, 2, E), 256>>>(wt_w, wt_b);
    fused_attn_combine_kernel<<<E * 256, 256, FUS_SMEM>>>();
    final_mma_kernel<<<dim3(8, 64), 256, FIN_SMEM>>>(wd_b, feats, scale, out);
}